// round 2
// baseline (speedup 1.0000x reference)
#include <cuda_runtime.h>
#include <math.h>

#define NN 50000
#define FE 800000
#define ET (FE + NN)
#define PAD 257

// ---------------- scratch (static device memory; no runtime allocation) ----
__device__ float g_h1[NN * 256];
__device__ float g_o1[NN * 256];
__device__ float g_as1[NN * 4];
__device__ float g_ad1[NN * 4];
__device__ float g_m1[NN * 4];
__device__ float g_d1[NN * 4];
__device__ float g_h2[NN * 64];
__device__ float g_o2[NN * 64];
__device__ float g_as2[NN];
__device__ float g_ad2[NN];
__device__ float g_m2[NN];
__device__ float g_d2[NN];
__device__ int   g_src[ET];
__device__ int   g_dst[ET];
__device__ int   g_is64;

// ---------------- helpers ---------------------------------------------------
__device__ __forceinline__ void atomicMaxF(float* addr, float v) {
    // monotone-toward-float-max under any interleaving
    if (v >= 0.f) atomicMax((int*)addr, __float_as_int(v));
    else          atomicMin((unsigned int*)addr, (unsigned int)__float_as_int(v));
}

__device__ __forceinline__ float lrelu(float v) { return v > 0.f ? v : 0.2f * v; }
__device__ __forceinline__ float elu(float v)   { return v > 0.f ? v : expm1f(v); }

// ---------------- edge-index normalization ----------------------------------
// Detect whether d_in[1] is int32 or int64. If int64 (little-endian, values
// < 50000), every odd 32-bit word is a zero high-half. For int32, odd words
// are random node ids (prob. of 1024 consecutive zeros ~ (1/50000)^1024).
__global__ void k_detect(const int* __restrict__ ei32) {
    if (threadIdx.x == 0) {
        int nz = 0;
        for (int i = 0; i < 1024; i++) nz |= ei32[2 * i + 1];
        g_is64 = (nz == 0) ? 1 : 0;
    }
}
__global__ void k_convert(const int* __restrict__ ei32) {
    int i = blockIdx.x * blockDim.x + threadIdx.x;
    if (i >= ET) return;
    if (i < FE) {
        if (g_is64) { g_src[i] = ei32[2 * i]; g_dst[i] = ei32[2 * (FE + i)]; }
        else        { g_src[i] = ei32[i];     g_dst[i] = ei32[FE + i]; }
    } else {
        g_src[i] = i - FE; g_dst[i] = i - FE;   // self-loop
    }
}

// ---------------- layer 1: GEMM (N,16)x(16,256) + attention logits ---------
__global__ void k_gemm1(const float* __restrict__ x, const float* __restrict__ W1,
                        const float* __restrict__ as1, const float* __restrict__ ad1) {
    __shared__ float xs[16];
    __shared__ float red[256];
    int n = blockIdx.x, t = threadIdx.x;
    if (t < 16) xs[t] = x[n * 16 + t];
    __syncthreads();
    const float4* W4 = reinterpret_cast<const float4*>(W1) + t * 4;
    float4 w0 = W4[0], w1 = W4[1], w2 = W4[2], w3 = W4[3];
    float acc = xs[0] * w0.x + xs[1] * w0.y + xs[2] * w0.z + xs[3] * w0.w
              + xs[4] * w1.x + xs[5] * w1.y + xs[6] * w1.z + xs[7] * w1.w
              + xs[8] * w2.x + xs[9] * w2.y + xs[10] * w2.z + xs[11] * w2.w
              + xs[12] * w3.x + xs[13] * w3.y + xs[14] * w3.z + xs[15] * w3.w;
    g_h1[n * 256 + t] = acc;
    int h = t >> 6, c = t & 63;
    red[t] = acc * as1[t];   // att_src1 is [4][64], laid out exactly as t
    __syncthreads();
#pragma unroll
    for (int s = 32; s > 0; s >>= 1) { if (c < s) red[t] += red[t + s]; __syncthreads(); }
    if (c == 0) g_as1[n * 4 + h] = red[t];
    __syncthreads();
    red[t] = acc * ad1[t];
    __syncthreads();
#pragma unroll
    for (int s = 32; s > 0; s >>= 1) { if (c < s) red[t] += red[t + s]; __syncthreads(); }
    if (c == 0) g_ad1[n * 4 + h] = red[t];
}

// ---------------- init (must run every call: graph replays) -----------------
__global__ void k_init1() {
    int i = blockIdx.x * blockDim.x + threadIdx.x;
    if (i < NN * 256) g_o1[i] = 0.f;
    if (i < NN * 4) { g_m1[i] = -3.4e38f; g_d1[i] = 0.f; }
}
__global__ void k_init2() {
    int i = blockIdx.x * blockDim.x + threadIdx.x;
    if (i < NN * 64) g_o2[i] = 0.f;
    if (i < NN) { g_m2[i] = -3.4e38f; g_d2[i] = 0.f; }
}

// ---------------- layer 1 softmax passes ------------------------------------
__global__ void k_max1() {
    int i = blockIdx.x * blockDim.x + threadIdx.x;
    if (i >= ET * 4) return;
    int e = i >> 2, h = i & 3;
    int s = g_src[e], d = g_dst[e];
    float v = lrelu(g_as1[s * 4 + h] + g_ad1[d * 4 + h]);
    atomicMaxF(&g_m1[d * 4 + h], v);
}
__global__ void k_sum1() {
    int i = blockIdx.x * blockDim.x + threadIdx.x;
    if (i >= ET * 4) return;
    int e = i >> 2, h = i & 3;
    int s = g_src[e], d = g_dst[e];
    float v = lrelu(g_as1[s * 4 + h] + g_ad1[d * 4 + h]);
    atomicAdd(&g_d1[d * 4 + h], expf(v - g_m1[d * 4 + h]));
}
__global__ void k_agg1() {
    int e = blockIdx.x, t = threadIdx.x, h = t >> 6;
    int s = g_src[e], d = g_dst[e];
    float v = lrelu(g_as1[s * 4 + h] + g_ad1[d * 4 + h]);
    float w = expf(v - g_m1[d * 4 + h]) / (g_d1[d * 4 + h] + 1e-16f);
    atomicAdd(&g_o1[d * 256 + t], w * g_h1[s * 256 + t]);
}
__global__ void k_elu1(const float* __restrict__ b1) {
    int i = blockIdx.x * blockDim.x + threadIdx.x;
    if (i >= NN * 256) return;
    float v = g_o1[i] + b1[i & 255];
    g_h1[i] = elu(v);   // reuse g_h1 as layer-2 input
}

// ---------------- layer 2: GEMM (N,256)x(256,64) ----------------------------
__global__ void k_gemm2(const float* __restrict__ W2) {
    extern __shared__ float sm[];
    float* sW = sm;               // 64 x PAD (padded, conflict-free)
    float* sh = sm + 64 * PAD;    // 16 x 256
    int t = threadIdx.x;
    for (int i = t; i < 64 * 256; i += 256) sW[(i >> 8) * PAD + (i & 255)] = W2[i];
    int base = blockIdx.x * 16;
    for (int i = t; i < 16 * 256; i += 256) {
        sh[i] = g_h1[base * 256 + i];
    }
    __syncthreads();
    int o = t & 63, ng = t >> 6;
    const float* shp = sh + ng * 4 * 256;
    const float* swp = sW + o * PAD;
    float a0 = 0.f, a1 = 0.f, a2 = 0.f, a3 = 0.f;
#pragma unroll 8
    for (int k = 0; k < 256; k++) {
        float wv = swp[k];
        a0 += wv * shp[k];
        a1 += wv * shp[256 + k];
        a2 += wv * shp[512 + k];
        a3 += wv * shp[768 + k];
    }
    int n0 = base + ng * 4;
    g_h2[(n0 + 0) * 64 + o] = a0;
    g_h2[(n0 + 1) * 64 + o] = a1;
    g_h2[(n0 + 2) * 64 + o] = a2;
    g_h2[(n0 + 3) * 64 + o] = a3;
}

__global__ void k_alpha2(const float* __restrict__ as2, const float* __restrict__ ad2) {
    int g = blockIdx.x * blockDim.x + threadIdx.x;
    int n = g >> 5, lane = g & 31;
    if (n >= NN) return;
    float v0 = g_h2[n * 64 + lane], v1 = g_h2[n * 64 + 32 + lane];
    float a = v0 * as2[lane] + v1 * as2[32 + lane];
    float b = v0 * ad2[lane] + v1 * ad2[32 + lane];
#pragma unroll
    for (int s = 16; s > 0; s >>= 1) {
        a += __shfl_down_sync(0xffffffffu, a, s);
        b += __shfl_down_sync(0xffffffffu, b, s);
    }
    if (lane == 0) { g_as2[n] = a; g_ad2[n] = b; }
}

__global__ void k_max2() {
    int e = blockIdx.x * blockDim.x + threadIdx.x;
    if (e >= ET) return;
    int s = g_src[e], d = g_dst[e];
    float v = lrelu(g_as2[s] + g_ad2[d]);
    atomicMaxF(&g_m2[d], v);
}
__global__ void k_sum2() {
    int e = blockIdx.x * blockDim.x + threadIdx.x;
    if (e >= ET) return;
    int s = g_src[e], d = g_dst[e];
    float v = lrelu(g_as2[s] + g_ad2[d]);
    atomicAdd(&g_d2[d], expf(v - g_m2[d]));
}
__global__ void k_agg2() {
    int i = blockIdx.x * blockDim.x + threadIdx.x;
    if (i >= ET * 64) return;
    int e = i >> 6, c = i & 63;
    int s = g_src[e], d = g_dst[e];
    float v = lrelu(g_as2[s] + g_ad2[d]);
    float w = expf(v - g_m2[d]) / (g_d2[d] + 1e-16f);
    atomicAdd(&g_o2[d * 64 + c], w * g_h2[s * 64 + c]);
}
__global__ void k_elu2(const float* __restrict__ b2) {
    int i = blockIdx.x * blockDim.x + threadIdx.x;
    if (i >= NN * 64) return;
    float v = g_o2[i] + b2[i & 63];
    g_h2[i] = elu(v);   // reuse g_h2 as final input
}

// ---------------- final projection (64 -> 1) ---------------------------------
__global__ void k_final(const float* __restrict__ fw, const float* __restrict__ fb,
                        float* __restrict__ out) {
    int g = blockIdx.x * blockDim.x + threadIdx.x;
    int n = g >> 5, lane = g & 31;
    if (n >= NN) return;
    float v = g_h2[n * 64 + lane] * fw[lane] + g_h2[n * 64 + 32 + lane] * fw[32 + lane];
#pragma unroll
    for (int s = 16; s > 0; s >>= 1) v += __shfl_down_sync(0xffffffffu, v, s);
    if (lane == 0) out[n] = v + fb[0];
}

// ---------------- launch ------------------------------------------------------
extern "C" void kernel_launch(void* const* d_in, const int* in_sizes, int n_in,
                              void* d_out, int out_size) {
    const float* x   = (const float*)d_in[0];
    const int*   ei  = (const int*)d_in[1];   // int32 (JAX x64 disabled) or int64 (detected)
    const float* W1  = (const float*)d_in[2];
    const float* as1 = (const float*)d_in[3];
    const float* ad1 = (const float*)d_in[4];
    const float* b1  = (const float*)d_in[5];
    const float* W2  = (const float*)d_in[6];
    const float* as2 = (const float*)d_in[7];
    const float* ad2 = (const float*)d_in[8];
    const float* b2  = (const float*)d_in[9];
    const float* fw  = (const float*)d_in[10];
    const float* fb  = (const float*)d_in[11];
    float*       out = (float*)d_out;

    const int smem2 = (64 * PAD + 16 * 256) * (int)sizeof(float);  // 82176 B
    cudaFuncSetAttribute(k_gemm2, cudaFuncAttributeMaxDynamicSharedMemorySize, smem2);

    k_detect<<<1, 32>>>(ei);
    k_convert<<<(ET + 255) / 256, 256>>>(ei);
    k_gemm1<<<NN, 256>>>(x, W1, as1, ad1);
    k_init1<<<NN, 256>>>();                              // covers NN*256 exactly
    k_max1<<<(ET * 4 + 255) / 256, 256>>>();
    k_sum1<<<(ET * 4 + 255) / 256, 256>>>();
    k_agg1<<<ET, 256>>>();
    k_elu1<<<(NN * 256 + 255) / 256, 256>>>(b1);
    k_gemm2<<<NN / 16, 256, smem2>>>(W2);
    k_alpha2<<<(NN * 32 + 255) / 256, 256>>>(as2, ad2);
    k_init2<<<(NN * 64 + 255) / 256, 256>>>();
    k_max2<<<(ET + 255) / 256, 256>>>();
    k_sum2<<<(ET + 255) / 256, 256>>>();
    k_agg2<<<(ET * 64 + 255) / 256, 256>>>();
    k_elu2<<<(NN * 64 + 255) / 256, 256>>>(b2);
    k_final<<<(NN * 32 + 255) / 256, 256>>>(fw, fb, out);
}

// round 3
// speedup vs baseline: 2.0785x; 2.0785x over previous
#include <cuda_runtime.h>
#include <math.h>

#define NN 50000
#define FE 800000
#define ET (FE + NN)
#define PAD 257
#define NPART 196   // ceil(NN/256)

// ---------------- scratch ----------------------------------------------------
__device__ float g_h1[NN * 256];   // layer1 pre-act features h = x@W1^T
__device__ float g_o1[NN * 256];   // elu(layer1 out)  -> layer2 input
__device__ float g_as1[NN * 4];
__device__ float g_ad1[NN * 4];
__device__ float g_h2[NN * 64];    // layer2 pre-agg features
__device__ float g_o2[NN * 64];    // elu(layer2 out)
__device__ float g_as2[NN];
__device__ float g_ad2[NN];
__device__ int   g_src[ET];
__device__ int   g_dst[ET];
__device__ int   g_eid[ET];        // CSR column (src) indices grouped by dst
__device__ int   g_cnt[NN];
__device__ int   g_off[NN + 1];
__device__ int   g_cur[NN];
__device__ int   g_part[256];
__device__ int   g_partx[256];
__device__ int   g_is64;
__device__ float g_ws1s[64];       // folded att_src1: [4 heads][16]
__device__ float g_ws1d[64];
__device__ float g_v2s[256];       // folded att_src2 over W2
__device__ float g_v2d[256];

// ---------------- helpers -----------------------------------------------------
__device__ __forceinline__ float lrelu(float v) { return v > 0.f ? v : 0.2f * v; }
__device__ __forceinline__ float elu(float v)   { return v > 0.f ? v : expm1f(v); }
#define NEG_INF __int_as_float(0xff800000)

// ---------------- edge-index normalization + degree ---------------------------
__global__ void k_detect(const int* __restrict__ ei32) {
    if (threadIdx.x == 0) {
        int nz = 0;
        for (int i = 0; i < 1024; i++) nz |= ei32[2 * i + 1];
        g_is64 = (nz == 0) ? 1 : 0;
    }
}
__global__ void k_zero() {
    int i = blockIdx.x * blockDim.x + threadIdx.x;
    if (i < NN) g_cnt[i] = 0;
}
__global__ void k_convert(const int* __restrict__ ei32) {
    int i = blockIdx.x * blockDim.x + threadIdx.x;
    if (i >= ET) return;
    int s, d;
    if (i < FE) {
        if (g_is64) { s = ei32[2 * i]; d = ei32[2 * (FE + i)]; }
        else        { s = ei32[i];     d = ei32[FE + i]; }
    } else { s = i - FE; d = s; }
    g_src[i] = s; g_dst[i] = d;
    atomicAdd(&g_cnt[d], 1);
}

// ---------------- scan (CSR offsets) ------------------------------------------
__global__ void k_scan_part() {
    __shared__ int sm[256];
    int b = blockIdx.x, t = threadIdx.x, i = b * 256 + t;
    sm[t] = (i < NN) ? g_cnt[i] : 0;
    __syncthreads();
#pragma unroll
    for (int s = 128; s > 0; s >>= 1) { if (t < s) sm[t] += sm[t + s]; __syncthreads(); }
    if (t == 0) g_part[b] = sm[0];
}
__global__ void k_scan_mid() {
    __shared__ int sm[256];
    int t = threadIdx.x;
    int v = (t < NPART) ? g_part[t] : 0;
    sm[t] = v; __syncthreads();
#pragma unroll
    for (int s = 1; s < 256; s <<= 1) {
        int a = (t >= s) ? sm[t - s] : 0;
        __syncthreads(); sm[t] += a; __syncthreads();
    }
    g_partx[t] = sm[t] - v;       // exclusive
    if (t == 0) g_off[NN] = ET;
}
__global__ void k_scan_fin() {
    __shared__ int sm[256];
    int b = blockIdx.x, t = threadIdx.x, i = b * 256 + t;
    int v = (i < NN) ? g_cnt[i] : 0;
    sm[t] = v; __syncthreads();
#pragma unroll
    for (int s = 1; s < 256; s <<= 1) {
        int a = (t >= s) ? sm[t - s] : 0;
        __syncthreads(); sm[t] += a; __syncthreads();
    }
    if (i < NN) {
        int off = g_partx[b] + sm[t] - v;
        g_off[i] = off; g_cur[i] = off;
    }
}
__global__ void k_scatter() {
    int i = blockIdx.x * blockDim.x + threadIdx.x;
    if (i >= ET) return;
    int d = g_dst[i];
    int pos = atomicAdd(&g_cur[d], 1);
    g_eid[pos] = g_src[i];
}

// ---------------- fold attention vectors into weights --------------------------
__global__ void k_prew(const float* __restrict__ W1,
                       const float* __restrict__ as1, const float* __restrict__ ad1,
                       const float* __restrict__ W2,
                       const float* __restrict__ as2, const float* __restrict__ ad2) {
    int t = threadIdx.x;
    if (t < 64) {                      // layer1: ws[h][i] = sum_c a[h][c]*W1[(h*64+c)*16+i]
        int h = t >> 4, i = t & 15;
        float s = 0.f, d = 0.f;
        for (int c = 0; c < 64; c++) {
            float w = W1[(h * 64 + c) * 16 + i];
            s += as1[h * 64 + c] * w;
            d += ad1[h * 64 + c] * w;
        }
        g_ws1s[t] = s; g_ws1d[t] = d;
    }
    {                                  // layer2: v[k] = sum_o a[o]*W2[o*256+k]
        float s = 0.f, d = 0.f;
        for (int o = 0; o < 64; o++) {
            float w = W2[o * 256 + t];
            s += as2[o] * w;
            d += ad2[o] * w;
        }
        g_v2s[t] = s; g_v2d[t] = d;
    }
}

// ---------------- layer 1 GEMM: 8 nodes / block --------------------------------
__global__ void k_gemm1(const float* __restrict__ x, const float* __restrict__ W1) {
    __shared__ float xs[128];
    int t = threadIdx.x, b = blockIdx.x;
    if (t < 128) xs[t] = x[b * 128 + t];
    __syncthreads();
    const float4* W4 = reinterpret_cast<const float4*>(W1) + t * 4;
    float4 w0 = W4[0], w1 = W4[1], w2 = W4[2], w3 = W4[3];
#pragma unroll
    for (int j = 0; j < 8; j++) {
        const float* xv = xs + j * 16;
        float acc = xv[0] * w0.x + xv[1] * w0.y + xv[2] * w0.z + xv[3] * w0.w
                  + xv[4] * w1.x + xv[5] * w1.y + xv[6] * w1.z + xv[7] * w1.w
                  + xv[8] * w2.x + xv[9] * w2.y + xv[10] * w2.z + xv[11] * w2.w
                  + xv[12] * w3.x + xv[13] * w3.y + xv[14] * w3.z + xv[15] * w3.w;
        g_h1[(b * 8 + j) * 256 + t] = acc;
    }
}

// ---------------- layer 1 attention logits from x directly ---------------------
__global__ void k_alpha1(const float* __restrict__ x) {
    __shared__ float ws[64], wd[64];
    int t = threadIdx.x;
    if (t < 64) { ws[t] = g_ws1s[t]; wd[t] = g_ws1d[t]; }
    __syncthreads();
    int n = blockIdx.x * blockDim.x + t;
    if (n >= NN) return;
    const float4* xv = reinterpret_cast<const float4*>(x + n * 16);
    float4 x0 = xv[0], x1 = xv[1], x2 = xv[2], x3 = xv[3];
#pragma unroll
    for (int h = 0; h < 4; h++) {
        const float* s = ws + h * 16;
        const float* d = wd + h * 16;
        float a = x0.x * s[0] + x0.y * s[1] + x0.z * s[2] + x0.w * s[3]
                + x1.x * s[4] + x1.y * s[5] + x1.z * s[6] + x1.w * s[7]
                + x2.x * s[8] + x2.y * s[9] + x2.z * s[10] + x2.w * s[11]
                + x3.x * s[12] + x3.y * s[13] + x3.z * s[14] + x3.w * s[15];
        float b = x0.x * d[0] + x0.y * d[1] + x0.z * d[2] + x0.w * d[3]
                + x1.x * d[4] + x1.y * d[5] + x1.z * d[6] + x1.w * d[7]
                + x2.x * d[8] + x2.y * d[9] + x2.z * d[10] + x2.w * d[11]
                + x3.x * d[12] + x3.y * d[13] + x3.z * d[14] + x3.w * d[15];
        g_as1[n * 4 + h] = a;
        g_ad1[n * 4 + h] = b;
    }
}

// ---------------- layer 1 fused softmax + aggregate + bias + ELU ---------------
__global__ void k_fused1(const float* __restrict__ b1) {
    int d = blockIdx.x, t = threadIdx.x, h = t >> 6;
    int beg = g_off[d], end = g_off[d + 1];
    float ad = g_ad1[d * 4 + h];
    float m = NEG_INF, ssum = 0.f, acc = 0.f;
    int s = g_eid[beg];
    float e = lrelu(g_as1[s * 4 + h] + ad);
    float hv = g_h1[s * 256 + t];
    for (int k = beg; k < end; k++) {
        int k2 = k + 1;
        int s2 = 0; float e2 = 0.f, hv2 = 0.f;
        if (k2 < end) {                                   // prefetch next edge
            s2 = g_eid[k2];
            e2 = lrelu(g_as1[s2 * 4 + h] + ad);
            hv2 = g_h1[s2 * 256 + t];
        }
        float nm = fmaxf(m, e);
        float scale = expf(m - nm);                        // exp(-inf)=0 on first iter
        float w = expf(e - nm);
        ssum = ssum * scale + w;
        acc = acc * scale + w * hv;
        m = nm;
        e = e2; hv = hv2;
    }
    float v = acc / (ssum + 1e-16f) + b1[t];
    g_o1[d * 256 + t] = elu(v);
}

// ---------------- layer 2 GEMM (16 nodes/block) + logit epilogue ---------------
__global__ void k_gemm2(const float* __restrict__ W2) {
    extern __shared__ float sm[];
    float* sW = sm;               // 64 x PAD
    float* sh = sm + 64 * PAD;    // 16 x 256
    int t = threadIdx.x;
    for (int i = t; i < 64 * 256; i += 256) sW[(i >> 8) * PAD + (i & 255)] = W2[i];
    int base = blockIdx.x * 16;
    for (int i = t; i < 16 * 256; i += 256) sh[i] = g_o1[base * 256 + i];
    __syncthreads();
    int o = t & 63, ng = t >> 6;
    const float* shp = sh + ng * 4 * 256;
    const float* swp = sW + o * PAD;
    float a0 = 0.f, a1 = 0.f, a2 = 0.f, a3 = 0.f;
#pragma unroll 8
    for (int k = 0; k < 256; k++) {
        float wv = swp[k];
        a0 += wv * shp[k];
        a1 += wv * shp[256 + k];
        a2 += wv * shp[512 + k];
        a3 += wv * shp[768 + k];
    }
    int n0 = base + ng * 4;
    g_h2[(n0 + 0) * 64 + o] = a0;
    g_h2[(n0 + 1) * 64 + o] = a1;
    g_h2[(n0 + 2) * 64 + o] = a2;
    g_h2[(n0 + 3) * 64 + o] = a3;
    // epilogue: as2/ad2 = o1[n] . v2{s,d}  (tile already in smem)
    int tn = t >> 4, l = t & 15;
    float a = 0.f, b = 0.f;
    const float* row = sh + tn * 256;
    for (int k = l; k < 256; k += 16) {
        float vv = row[k];
        a += vv * g_v2s[k];
        b += vv * g_v2d[k];
    }
#pragma unroll
    for (int sft = 8; sft > 0; sft >>= 1) {
        a += __shfl_down_sync(0xffffffffu, a, sft, 16);
        b += __shfl_down_sync(0xffffffffu, b, sft, 16);
    }
    if (l == 0) { g_as2[base + tn] = a; g_ad2[base + tn] = b; }
}

// ---------------- layer 2 fused softmax + aggregate + bias + ELU ---------------
__global__ void k_fused2(const float* __restrict__ b2) {
    int d = blockIdx.x * 2 + (threadIdx.x >> 6);
    int c = threadIdx.x & 63;
    int beg = g_off[d], end = g_off[d + 1];
    float ad = g_ad2[d];
    float m = NEG_INF, ssum = 0.f, acc = 0.f;
    int s = g_eid[beg];
    float e = lrelu(g_as2[s] + ad);
    float hv = g_h2[s * 64 + c];
    for (int k = beg; k < end; k++) {
        int k2 = k + 1;
        int s2 = 0; float e2 = 0.f, hv2 = 0.f;
        if (k2 < end) {
            s2 = g_eid[k2];
            e2 = lrelu(g_as2[s2] + ad);
            hv2 = g_h2[s2 * 64 + c];
        }
        float nm = fmaxf(m, e);
        float scale = expf(m - nm);
        float w = expf(e - nm);
        ssum = ssum * scale + w;
        acc = acc * scale + w * hv;
        m = nm;
        e = e2; hv = hv2;
    }
    float v = acc / (ssum + 1e-16f) + b2[c];
    g_o2[d * 64 + c] = elu(v);
}

// ---------------- final projection (64 -> 1) ------------------------------------
__global__ void k_final(const float* __restrict__ fw, const float* __restrict__ fb,
                        float* __restrict__ out) {
    int g = blockIdx.x * blockDim.x + threadIdx.x;
    int n = g >> 5, lane = g & 31;
    if (n >= NN) return;
    float v = g_o2[n * 64 + lane] * fw[lane] + g_o2[n * 64 + 32 + lane] * fw[32 + lane];
#pragma unroll
    for (int s = 16; s > 0; s >>= 1) v += __shfl_down_sync(0xffffffffu, v, s);
    if (lane == 0) out[n] = v + fb[0];
}

// ---------------- launch ---------------------------------------------------------
extern "C" void kernel_launch(void* const* d_in, const int* in_sizes, int n_in,
                              void* d_out, int out_size) {
    const float* x   = (const float*)d_in[0];
    const int*   ei  = (const int*)d_in[1];
    const float* W1  = (const float*)d_in[2];
    const float* as1 = (const float*)d_in[3];
    const float* ad1 = (const float*)d_in[4];
    const float* b1  = (const float*)d_in[5];
    const float* W2  = (const float*)d_in[6];
    const float* as2 = (const float*)d_in[7];
    const float* ad2 = (const float*)d_in[8];
    const float* b2  = (const float*)d_in[9];
    const float* fw  = (const float*)d_in[10];
    const float* fb  = (const float*)d_in[11];
    float*       out = (float*)d_out;

    const int smem2 = (64 * PAD + 16 * 256) * (int)sizeof(float);  // 82176 B
    cudaFuncSetAttribute(k_gemm2, cudaFuncAttributeMaxDynamicSharedMemorySize, smem2);

    k_detect<<<1, 32>>>(ei);
    k_zero<<<NPART, 256>>>();
    k_convert<<<(ET + 255) / 256, 256>>>(ei);
    k_scan_part<<<NPART, 256>>>();
    k_scan_mid<<<1, 256>>>();
    k_scan_fin<<<NPART, 256>>>();
    k_scatter<<<(ET + 255) / 256, 256>>>();
    k_prew<<<1, 256>>>(W1, as1, ad1, W2, as2, ad2);
    k_gemm1<<<NN / 8, 256>>>(x, W1);
    k_alpha1<<<(NN + 63) / 64, 64>>>(x);
    k_fused1<<<NN, 256>>>(b1);
    k_gemm2<<<NN / 16, 256, smem2>>>(W2);
    k_fused2<<<NN / 2, 128>>>(b2);
    k_final<<<(NN * 32 + 255) / 256, 256>>>(fw, fb, out);
}

// round 4
// speedup vs baseline: 2.9023x; 1.3963x over previous
#include <cuda_runtime.h>
#include <math.h>

#define NN 50000
#define FE 800000
#define ET (FE + NN)
#define PAD 257
#define NPART 196   // ceil(NN/256)

// ---------------- scratch ----------------------------------------------------
__device__ float g_h1[NN * 256];   // layer1 features h = x@W1^T
__device__ float g_o1[NN * 256];   // elu(layer1 out)  -> layer2 input
__device__ float g_as1[NN * 4];
__device__ float g_ad1[NN * 4];
__device__ float g_h2[NN * 64];
__device__ float g_o2[NN * 64];
__device__ float g_as2[NN];
__device__ float g_ad2[NN];
__device__ float g_w1[ET * 4];     // unnormalized softmax weights (layer1, per head)
__device__ float g_inv1[NN * 4];   // 1/(denom+eps)
__device__ float g_w2[ET];
__device__ float g_inv2[NN];
__device__ int   g_src[ET];
__device__ int   g_dst[ET];
__device__ int   g_eid[ET];        // CSR src ids grouped by dst
__device__ int   g_cnt[NN];
__device__ int   g_off[NN + 1];
__device__ int   g_cur[NN];
__device__ int   g_part[256];
__device__ int   g_partx[256];
__device__ int   g_is64;
__device__ float g_ws1s[64];
__device__ float g_ws1d[64];
__device__ float g_v2s[256];
__device__ float g_v2d[256];

__device__ __forceinline__ float lrelu(float v) { return v > 0.f ? v : 0.2f * v; }
__device__ __forceinline__ float elu(float v)   { return v > 0.f ? v : expm1f(v); }
#define NEG_INF __int_as_float(0xff800000)

// ---------------- edge-index normalization + degree ---------------------------
__global__ void k_detect(const int* __restrict__ ei32) {
    if (threadIdx.x == 0) {
        int nz = 0;
        for (int i = 0; i < 1024; i++) nz |= ei32[2 * i + 1];
        g_is64 = (nz == 0) ? 1 : 0;
    }
}
__global__ void k_zero() {
    int i = blockIdx.x * blockDim.x + threadIdx.x;
    if (i < NN) g_cnt[i] = 0;
}
__global__ void k_convert(const int* __restrict__ ei32) {
    int i = blockIdx.x * blockDim.x + threadIdx.x;
    if (i >= ET) return;
    int s, d;
    if (i < FE) {
        if (g_is64) { s = ei32[2 * i]; d = ei32[2 * (FE + i)]; }
        else        { s = ei32[i];     d = ei32[FE + i]; }
    } else { s = i - FE; d = s; }
    g_src[i] = s; g_dst[i] = d;
    atomicAdd(&g_cnt[d], 1);
}

// ---------------- scan (CSR offsets) ------------------------------------------
__global__ void k_scan_part() {
    __shared__ int sm[256];
    int b = blockIdx.x, t = threadIdx.x, i = b * 256 + t;
    sm[t] = (i < NN) ? g_cnt[i] : 0;
    __syncthreads();
#pragma unroll
    for (int s = 128; s > 0; s >>= 1) { if (t < s) sm[t] += sm[t + s]; __syncthreads(); }
    if (t == 0) g_part[b] = sm[0];
}
__global__ void k_scan_mid() {
    __shared__ int sm[256];
    int t = threadIdx.x;
    int v = (t < NPART) ? g_part[t] : 0;
    sm[t] = v; __syncthreads();
#pragma unroll
    for (int s = 1; s < 256; s <<= 1) {
        int a = (t >= s) ? sm[t - s] : 0;
        __syncthreads(); sm[t] += a; __syncthreads();
    }
    g_partx[t] = sm[t] - v;
    if (t == 0) g_off[NN] = ET;
}
__global__ void k_scan_fin() {
    __shared__ int sm[256];
    int b = blockIdx.x, t = threadIdx.x, i = b * 256 + t;
    int v = (i < NN) ? g_cnt[i] : 0;
    sm[t] = v; __syncthreads();
#pragma unroll
    for (int s = 1; s < 256; s <<= 1) {
        int a = (t >= s) ? sm[t - s] : 0;
        __syncthreads(); sm[t] += a; __syncthreads();
    }
    if (i < NN) {
        int off = g_partx[b] + sm[t] - v;
        g_off[i] = off; g_cur[i] = off;
    }
}
__global__ void k_scatter() {
    int i = blockIdx.x * blockDim.x + threadIdx.x;
    if (i >= ET) return;
    int d = g_dst[i];
    int pos = atomicAdd(&g_cur[d], 1);
    g_eid[pos] = g_src[i];
}

// ---------------- fold attention vectors into weights --------------------------
__global__ void k_prew(const float* __restrict__ W1,
                       const float* __restrict__ as1, const float* __restrict__ ad1,
                       const float* __restrict__ W2,
                       const float* __restrict__ as2, const float* __restrict__ ad2) {
    int t = threadIdx.x;
    if (t < 64) {
        int h = t >> 4, i = t & 15;
        float s = 0.f, d = 0.f;
        for (int c = 0; c < 64; c++) {
            float w = W1[(h * 64 + c) * 16 + i];
            s += as1[h * 64 + c] * w;
            d += ad1[h * 64 + c] * w;
        }
        g_ws1s[t] = s; g_ws1d[t] = d;
    }
    {
        float s = 0.f, d = 0.f;
        for (int o = 0; o < 64; o++) {
            float w = W2[o * 256 + t];
            s += as2[o] * w;
            d += ad2[o] * w;
        }
        g_v2s[t] = s; g_v2d[t] = d;
    }
}

// ---------------- layer 1 GEMM: 8 nodes / block --------------------------------
__global__ void k_gemm1(const float* __restrict__ x, const float* __restrict__ W1) {
    __shared__ float xs[128];
    int t = threadIdx.x, b = blockIdx.x;
    if (t < 128) xs[t] = x[b * 128 + t];
    __syncthreads();
    const float4* W4 = reinterpret_cast<const float4*>(W1) + t * 4;
    float4 w0 = W4[0], w1 = W4[1], w2 = W4[2], w3 = W4[3];
#pragma unroll
    for (int j = 0; j < 8; j++) {
        const float* xv = xs + j * 16;
        float acc = xv[0] * w0.x + xv[1] * w0.y + xv[2] * w0.z + xv[3] * w0.w
                  + xv[4] * w1.x + xv[5] * w1.y + xv[6] * w1.z + xv[7] * w1.w
                  + xv[8] * w2.x + xv[9] * w2.y + xv[10] * w2.z + xv[11] * w2.w
                  + xv[12] * w3.x + xv[13] * w3.y + xv[14] * w3.z + xv[15] * w3.w;
        g_h1[(b * 8 + j) * 256 + t] = acc;
    }
}

// ---------------- layer 1 attention logits from x directly ---------------------
__global__ void k_alpha1(const float* __restrict__ x) {
    __shared__ float ws[64], wd[64];
    int t = threadIdx.x;
    if (t < 64) { ws[t] = g_ws1s[t]; wd[t] = g_ws1d[t]; }
    __syncthreads();
    int n = blockIdx.x * blockDim.x + t;
    if (n >= NN) return;
    const float4* xv = reinterpret_cast<const float4*>(x + n * 16);
    float4 x0 = xv[0], x1 = xv[1], x2 = xv[2], x3 = xv[3];
#pragma unroll
    for (int h = 0; h < 4; h++) {
        const float* s = ws + h * 16;
        const float* d = wd + h * 16;
        float a = x0.x * s[0] + x0.y * s[1] + x0.z * s[2] + x0.w * s[3]
                + x1.x * s[4] + x1.y * s[5] + x1.z * s[6] + x1.w * s[7]
                + x2.x * s[8] + x2.y * s[9] + x2.z * s[10] + x2.w * s[11]
                + x3.x * s[12] + x3.y * s[13] + x3.z * s[14] + x3.w * s[15];
        float b = x0.x * d[0] + x0.y * d[1] + x0.z * d[2] + x0.w * d[3]
                + x1.x * d[4] + x1.y * d[5] + x1.z * d[6] + x1.w * d[7]
                + x2.x * d[8] + x2.y * d[9] + x2.z * d[10] + x2.w * d[11]
                + x3.x * d[12] + x3.y * d[13] + x3.z * d[14] + x3.w * d[15];
        g_as1[n * 4 + h] = a;
        g_ad1[n * 4 + h] = b;
    }
}

// ---------------- layer 1 softmax weights: warp per dst -------------------------
__global__ void k_w1() {
    int d = blockIdx.x * 4 + (threadIdx.x >> 5);
    if (d >= NN) return;
    int lane = threadIdx.x & 31;
    int beg = g_off[d], end = g_off[d + 1];
    const float4 adv = *reinterpret_cast<const float4*>(&g_ad1[d * 4]);
    float m0 = NEG_INF, m1 = NEG_INF, m2 = NEG_INF, m3 = NEG_INF;
    for (int k = beg + lane; k < end; k += 32) {
        int s = g_eid[k];
        float4 as = *reinterpret_cast<const float4*>(&g_as1[s * 4]);
        m0 = fmaxf(m0, lrelu(as.x + adv.x));
        m1 = fmaxf(m1, lrelu(as.y + adv.y));
        m2 = fmaxf(m2, lrelu(as.z + adv.z));
        m3 = fmaxf(m3, lrelu(as.w + adv.w));
    }
#pragma unroll
    for (int o = 16; o > 0; o >>= 1) {
        m0 = fmaxf(m0, __shfl_xor_sync(0xffffffffu, m0, o));
        m1 = fmaxf(m1, __shfl_xor_sync(0xffffffffu, m1, o));
        m2 = fmaxf(m2, __shfl_xor_sync(0xffffffffu, m2, o));
        m3 = fmaxf(m3, __shfl_xor_sync(0xffffffffu, m3, o));
    }
    float s0 = 0.f, s1 = 0.f, s2 = 0.f, s3 = 0.f;
    for (int k = beg + lane; k < end; k += 32) {
        int s = g_eid[k];
        float4 as = *reinterpret_cast<const float4*>(&g_as1[s * 4]);
        float w0 = expf(lrelu(as.x + adv.x) - m0);
        float w1 = expf(lrelu(as.y + adv.y) - m1);
        float w2 = expf(lrelu(as.z + adv.z) - m2);
        float w3 = expf(lrelu(as.w + adv.w) - m3);
        *reinterpret_cast<float4*>(&g_w1[k * 4]) = make_float4(w0, w1, w2, w3);
        s0 += w0; s1 += w1; s2 += w2; s3 += w3;
    }
#pragma unroll
    for (int o = 16; o > 0; o >>= 1) {
        s0 += __shfl_xor_sync(0xffffffffu, s0, o);
        s1 += __shfl_xor_sync(0xffffffffu, s1, o);
        s2 += __shfl_xor_sync(0xffffffffu, s2, o);
        s3 += __shfl_xor_sync(0xffffffffu, s3, o);
    }
    if (lane == 0) {
        *reinterpret_cast<float4*>(&g_inv1[d * 4]) =
            make_float4(1.f / (s0 + 1e-16f), 1.f / (s1 + 1e-16f),
                        1.f / (s2 + 1e-16f), 1.f / (s3 + 1e-16f));
    }
}

// ---------------- layer 1 aggregation: block per dst, MLP-4 ---------------------
__global__ void k_agg1(const float* __restrict__ b1) {
    int d = blockIdx.x, t = threadIdx.x, h = t >> 6;
    int beg = g_off[d], end = g_off[d + 1];
    float acc0 = 0.f, acc1 = 0.f;
    int k = beg;
    for (; k + 4 <= end; k += 4) {
        int s0 = g_eid[k], s1 = g_eid[k + 1], s2 = g_eid[k + 2], s3 = g_eid[k + 3];
        float w0 = g_w1[(k + 0) * 4 + h];
        float w1 = g_w1[(k + 1) * 4 + h];
        float w2 = g_w1[(k + 2) * 4 + h];
        float w3 = g_w1[(k + 3) * 4 + h];
        float v0 = g_h1[s0 * 256 + t];
        float v1 = g_h1[s1 * 256 + t];
        float v2 = g_h1[s2 * 256 + t];
        float v3 = g_h1[s3 * 256 + t];
        acc0 += w0 * v0 + w2 * v2;
        acc1 += w1 * v1 + w3 * v3;
    }
    for (; k < end; k++) {
        int s = g_eid[k];
        acc0 += g_w1[k * 4 + h] * g_h1[s * 256 + t];
    }
    float inv = g_inv1[d * 4 + h];
    g_o1[d * 256 + t] = elu((acc0 + acc1) * inv + b1[t]);
}

// ---------------- layer 2 GEMM (16 nodes/block) + logit epilogue ----------------
__global__ void k_gemm2(const float* __restrict__ W2) {
    extern __shared__ float sm[];
    float* sW = sm;               // 64 x PAD
    float* sh = sm + 64 * PAD;    // 16 x 256
    int t = threadIdx.x;
    for (int i = t; i < 64 * 256; i += 256) sW[(i >> 8) * PAD + (i & 255)] = W2[i];
    int base = blockIdx.x * 16;
    for (int i = t; i < 16 * 256; i += 256) sh[i] = g_o1[base * 256 + i];
    __syncthreads();
    int o = t & 63, ng = t >> 6;
    const float* shp = sh + ng * 4 * 256;
    const float* swp = sW + o * PAD;
    float a0 = 0.f, a1 = 0.f, a2 = 0.f, a3 = 0.f;
#pragma unroll 8
    for (int k = 0; k < 256; k++) {
        float wv = swp[k];
        a0 += wv * shp[k];
        a1 += wv * shp[256 + k];
        a2 += wv * shp[512 + k];
        a3 += wv * shp[768 + k];
    }
    int n0 = base + ng * 4;
    g_h2[(n0 + 0) * 64 + o] = a0;
    g_h2[(n0 + 1) * 64 + o] = a1;
    g_h2[(n0 + 2) * 64 + o] = a2;
    g_h2[(n0 + 3) * 64 + o] = a3;
    int tn = t >> 4, l = t & 15;
    float a = 0.f, b = 0.f;
    const float* row = sh + tn * 256;
    for (int kk = l; kk < 256; kk += 16) {
        float vv = row[kk];
        a += vv * g_v2s[kk];
        b += vv * g_v2d[kk];
    }
#pragma unroll
    for (int sft = 8; sft > 0; sft >>= 1) {
        a += __shfl_down_sync(0xffffffffu, a, sft, 16);
        b += __shfl_down_sync(0xffffffffu, b, sft, 16);
    }
    if (l == 0) { g_as2[base + tn] = a; g_ad2[base + tn] = b; }
}

// ---------------- layer 2 softmax weights: warp per dst -------------------------
__global__ void k_w2() {
    int d = blockIdx.x * 4 + (threadIdx.x >> 5);
    if (d >= NN) return;
    int lane = threadIdx.x & 31;
    int beg = g_off[d], end = g_off[d + 1];
    float ad = g_ad2[d];
    float m = NEG_INF;
    for (int k = beg + lane; k < end; k += 32)
        m = fmaxf(m, lrelu(g_as2[g_eid[k]] + ad));
#pragma unroll
    for (int o = 16; o > 0; o >>= 1) m = fmaxf(m, __shfl_xor_sync(0xffffffffu, m, o));
    float ssum = 0.f;
    for (int k = beg + lane; k < end; k += 32) {
        float w = expf(lrelu(g_as2[g_eid[k]] + ad) - m);
        g_w2[k] = w;
        ssum += w;
    }
#pragma unroll
    for (int o = 16; o > 0; o >>= 1) ssum += __shfl_xor_sync(0xffffffffu, ssum, o);
    if (lane == 0) g_inv2[d] = 1.f / (ssum + 1e-16f);
}

// ---------------- layer 2 aggregation: 2 dst / block, MLP-4 ---------------------
__global__ void k_agg2(const float* __restrict__ b2) {
    int d = blockIdx.x * 2 + (threadIdx.x >> 6);
    int c = threadIdx.x & 63;
    int beg = g_off[d], end = g_off[d + 1];
    float acc0 = 0.f, acc1 = 0.f;
    int k = beg;
    for (; k + 4 <= end; k += 4) {
        int s0 = g_eid[k], s1 = g_eid[k + 1], s2 = g_eid[k + 2], s3 = g_eid[k + 3];
        float w0 = g_w2[k], w1 = g_w2[k + 1], w2 = g_w2[k + 2], w3 = g_w2[k + 3];
        float v0 = g_h2[s0 * 64 + c];
        float v1 = g_h2[s1 * 64 + c];
        float v2 = g_h2[s2 * 64 + c];
        float v3 = g_h2[s3 * 64 + c];
        acc0 += w0 * v0 + w2 * v2;
        acc1 += w1 * v1 + w3 * v3;
    }
    for (; k < end; k++) acc0 += g_w2[k] * g_h2[g_eid[k] * 64 + c];
    g_o2[d * 64 + c] = elu((acc0 + acc1) * g_inv2[d] + b2[c]);
}

// ---------------- final projection (64 -> 1) ------------------------------------
__global__ void k_final(const float* __restrict__ fw, const float* __restrict__ fb,
                        float* __restrict__ out) {
    int g = blockIdx.x * blockDim.x + threadIdx.x;
    int n = g >> 5, lane = g & 31;
    if (n >= NN) return;
    float v = g_o2[n * 64 + lane] * fw[lane] + g_o2[n * 64 + 32 + lane] * fw[32 + lane];
#pragma unroll
    for (int s = 16; s > 0; s >>= 1) v += __shfl_down_sync(0xffffffffu, v, s);
    if (lane == 0) out[n] = v + fb[0];
}

// ---------------- launch ---------------------------------------------------------
extern "C" void kernel_launch(void* const* d_in, const int* in_sizes, int n_in,
                              void* d_out, int out_size) {
    const float* x   = (const float*)d_in[0];
    const int*   ei  = (const int*)d_in[1];
    const float* W1  = (const float*)d_in[2];
    const float* as1 = (const float*)d_in[3];
    const float* ad1 = (const float*)d_in[4];
    const float* b1  = (const float*)d_in[5];
    const float* W2  = (const float*)d_in[6];
    const float* as2 = (const float*)d_in[7];
    const float* ad2 = (const float*)d_in[8];
    const float* b2  = (const float*)d_in[9];
    const float* fw  = (const float*)d_in[10];
    const float* fb  = (const float*)d_in[11];
    float*       out = (float*)d_out;

    const int smem2 = (64 * PAD + 16 * 256) * (int)sizeof(float);  // 82176 B
    cudaFuncSetAttribute(k_gemm2, cudaFuncAttributeMaxDynamicSharedMemorySize, smem2);

    k_detect<<<1, 32>>>(ei);
    k_zero<<<NPART, 256>>>();
    k_convert<<<(ET + 255) / 256, 256>>>(ei);
    k_scan_part<<<NPART, 256>>>();
    k_scan_mid<<<1, 256>>>();
    k_scan_fin<<<NPART, 256>>>();
    k_scatter<<<(ET + 255) / 256, 256>>>();
    k_prew<<<1, 256>>>(W1, as1, ad1, W2, as2, ad2);
    k_gemm1<<<NN / 8, 256>>>(x, W1);
    k_alpha1<<<(NN + 63) / 64, 64>>>(x);
    k_w1<<<(NN + 3) / 4, 128>>>();
    k_agg1<<<NN, 256>>>(b1);
    k_gemm2<<<NN / 16, 256, smem2>>>(W2);
    k_w2<<<(NN + 3) / 4, 128>>>();
    k_agg2<<<NN / 2, 128>>>(b2);
    k_final<<<(NN * 32 + 255) / 256, 256>>>(fw, fb, out);
}

// round 5
// speedup vs baseline: 4.8811x; 1.6818x over previous
#include <cuda_runtime.h>
#include <cuda_fp16.h>
#include <math.h>

#define NN 50000
#define NN2 50048          // padded to multiple of 64 for gemm2 tiles
#define FE 800000
#define ET (FE + NN)
#define NPART 196          // ceil(NN/256)

// ---------------- scratch ----------------------------------------------------
__device__ __half2 g_h1h[NN * 128];   // layer1 features (fp16), gather-only
__device__ float g_o1[NN2 * 256];     // elu(layer1 out) -> layer2 input (padded)
__device__ float g_as1[NN * 4];
__device__ float g_ad1[NN * 4];
__device__ float g_h2[NN2 * 64];      // layer2 pre-agg features (padded)
__device__ float g_o2[NN * 64];
__device__ float g_as2[NN];
__device__ float g_ad2[NN];
__device__ float g_w1[ET * 4];
__device__ float g_inv1[NN * 4];
__device__ float g_w2[ET];
__device__ float g_inv2[NN];
__device__ int   g_src[ET];
__device__ int   g_dst[ET];
__device__ int   g_eid[ET];
__device__ int   g_cnt[NN];
__device__ int   g_off[NN + 1];
__device__ int   g_cur[NN];
__device__ int   g_part[256];
__device__ int   g_partx[256];
__device__ int   g_is64;
__device__ float g_ws1s[64];
__device__ float g_ws1d[64];
__device__ float g_v2s[256];
__device__ float g_v2d[256];

__device__ __forceinline__ float lrelu(float v) { return v > 0.f ? v : 0.2f * v; }
__device__ __forceinline__ float elu(float v)   { return v > 0.f ? v : expm1f(v); }
#define NEG_INF __int_as_float(0xff800000)

// ---------------- edge-index normalization + degree ---------------------------
__global__ void k_detect(const int* __restrict__ ei32) {
    if (threadIdx.x == 0) {
        int nz = 0;
        for (int i = 0; i < 1024; i++) nz |= ei32[2 * i + 1];
        g_is64 = (nz == 0) ? 1 : 0;
    }
}
__global__ void k_zero() {
    int i = blockIdx.x * blockDim.x + threadIdx.x;
    if (i < NN) g_cnt[i] = 0;
}
__global__ void k_convert(const int* __restrict__ ei32) {
    int i = blockIdx.x * blockDim.x + threadIdx.x;
    if (i >= ET) return;
    int s, d;
    if (i < FE) {
        if (g_is64) { s = ei32[2 * i]; d = ei32[2 * (FE + i)]; }
        else        { s = ei32[i];     d = ei32[FE + i]; }
    } else { s = i - FE; d = s; }
    g_src[i] = s; g_dst[i] = d;
    atomicAdd(&g_cnt[d], 1);
}

// ---------------- scan (CSR offsets) ------------------------------------------
__global__ void k_scan_part() {
    __shared__ int sm[256];
    int b = blockIdx.x, t = threadIdx.x, i = b * 256 + t;
    sm[t] = (i < NN) ? g_cnt[i] : 0;
    __syncthreads();
#pragma unroll
    for (int s = 128; s > 0; s >>= 1) { if (t < s) sm[t] += sm[t + s]; __syncthreads(); }
    if (t == 0) g_part[b] = sm[0];
}
__global__ void k_scan_mid() {
    __shared__ int sm[256];
    int t = threadIdx.x;
    int v = (t < NPART) ? g_part[t] : 0;
    sm[t] = v; __syncthreads();
#pragma unroll
    for (int s = 1; s < 256; s <<= 1) {
        int a = (t >= s) ? sm[t - s] : 0;
        __syncthreads(); sm[t] += a; __syncthreads();
    }
    g_partx[t] = sm[t] - v;
    if (t == 0) g_off[NN] = ET;
}
__global__ void k_scan_fin() {
    __shared__ int sm[256];
    int b = blockIdx.x, t = threadIdx.x, i = b * 256 + t;
    int v = (i < NN) ? g_cnt[i] : 0;
    sm[t] = v; __syncthreads();
#pragma unroll
    for (int s = 1; s < 256; s <<= 1) {
        int a = (t >= s) ? sm[t - s] : 0;
        __syncthreads(); sm[t] += a; __syncthreads();
    }
    if (i < NN) {
        int off = g_partx[b] + sm[t] - v;
        g_off[i] = off; g_cur[i] = off;
    }
}
__global__ void k_scatter() {
    int i = blockIdx.x * blockDim.x + threadIdx.x;
    if (i >= ET) return;
    int d = g_dst[i];
    int pos = atomicAdd(&g_cur[d], 1);
    g_eid[pos] = g_src[i];
}

// ---------------- fold attention vectors into weights --------------------------
__global__ void k_prew(const float* __restrict__ W1,
                       const float* __restrict__ as1, const float* __restrict__ ad1,
                       const float* __restrict__ W2,
                       const float* __restrict__ as2, const float* __restrict__ ad2) {
    int t = threadIdx.x;
    if (t < 64) {
        int h = t >> 4, i = t & 15;
        float s = 0.f, d = 0.f;
        for (int c = 0; c < 64; c++) {
            float w = W1[(h * 64 + c) * 16 + i];
            s += as1[h * 64 + c] * w;
            d += ad1[h * 64 + c] * w;
        }
        g_ws1s[t] = s; g_ws1d[t] = d;
    }
    {
        float s = 0.f, d = 0.f;
        for (int o = 0; o < 64; o++) {
            float w = W2[o * 256 + t];
            s += as2[o] * w;
            d += ad2[o] * w;
        }
        g_v2s[t] = s; g_v2d[t] = d;
    }
}

// ---------------- layer 1 GEMM: 8 nodes / block, fp16 output -------------------
__global__ void k_gemm1(const float* __restrict__ x, const float* __restrict__ W1) {
    __shared__ float xs[128];
    int t = threadIdx.x, b = blockIdx.x;
    if (t < 128) xs[t] = x[b * 128 + t];
    __syncthreads();
    const float4* W4 = reinterpret_cast<const float4*>(W1) + t * 4;
    float4 w0 = W4[0], w1 = W4[1], w2 = W4[2], w3 = W4[3];
#pragma unroll
    for (int j = 0; j < 8; j++) {
        const float* xv = xs + j * 16;
        float acc = xv[0] * w0.x + xv[1] * w0.y + xv[2] * w0.z + xv[3] * w0.w
                  + xv[4] * w1.x + xv[5] * w1.y + xv[6] * w1.z + xv[7] * w1.w
                  + xv[8] * w2.x + xv[9] * w2.y + xv[10] * w2.z + xv[11] * w2.w
                  + xv[12] * w3.x + xv[13] * w3.y + xv[14] * w3.z + xv[15] * w3.w;
        float hi = __shfl_down_sync(0xffffffffu, acc, 1);
        if (!(t & 1)) g_h1h[(b * 8 + j) * 128 + (t >> 1)] = __floats2half2_rn(acc, hi);
    }
}

// ---------------- layer 1 attention logits from x directly ---------------------
__global__ void k_alpha1(const float* __restrict__ x) {
    __shared__ float ws[64], wd[64];
    int t = threadIdx.x;
    if (t < 64) { ws[t] = g_ws1s[t]; wd[t] = g_ws1d[t]; }
    __syncthreads();
    int n = blockIdx.x * blockDim.x + t;
    if (n >= NN) return;
    const float4* xv = reinterpret_cast<const float4*>(x + n * 16);
    float4 x0 = xv[0], x1 = xv[1], x2 = xv[2], x3 = xv[3];
#pragma unroll
    for (int h = 0; h < 4; h++) {
        const float* s = ws + h * 16;
        const float* d = wd + h * 16;
        float a = x0.x * s[0] + x0.y * s[1] + x0.z * s[2] + x0.w * s[3]
                + x1.x * s[4] + x1.y * s[5] + x1.z * s[6] + x1.w * s[7]
                + x2.x * s[8] + x2.y * s[9] + x2.z * s[10] + x2.w * s[11]
                + x3.x * s[12] + x3.y * s[13] + x3.z * s[14] + x3.w * s[15];
        float b = x0.x * d[0] + x0.y * d[1] + x0.z * d[2] + x0.w * d[3]
                + x1.x * d[4] + x1.y * d[5] + x1.z * d[6] + x1.w * d[7]
                + x2.x * d[8] + x2.y * d[9] + x2.z * d[10] + x2.w * d[11]
                + x3.x * d[12] + x3.y * d[13] + x3.z * d[14] + x3.w * d[15];
        g_as1[n * 4 + h] = a;
        g_ad1[n * 4 + h] = b;
    }
}

// ---------------- layer 1 softmax weights: warp per dst -------------------------
__global__ void k_w1() {
    int d = blockIdx.x * 4 + (threadIdx.x >> 5);
    if (d >= NN) return;
    int lane = threadIdx.x & 31;
    int beg = g_off[d], end = g_off[d + 1];
    const float4 adv = *reinterpret_cast<const float4*>(&g_ad1[d * 4]);
    float m0 = NEG_INF, m1 = NEG_INF, m2 = NEG_INF, m3 = NEG_INF;
    for (int k = beg + lane; k < end; k += 32) {
        int s = g_eid[k];
        float4 as = *reinterpret_cast<const float4*>(&g_as1[s * 4]);
        m0 = fmaxf(m0, lrelu(as.x + adv.x));
        m1 = fmaxf(m1, lrelu(as.y + adv.y));
        m2 = fmaxf(m2, lrelu(as.z + adv.z));
        m3 = fmaxf(m3, lrelu(as.w + adv.w));
    }
#pragma unroll
    for (int o = 16; o > 0; o >>= 1) {
        m0 = fmaxf(m0, __shfl_xor_sync(0xffffffffu, m0, o));
        m1 = fmaxf(m1, __shfl_xor_sync(0xffffffffu, m1, o));
        m2 = fmaxf(m2, __shfl_xor_sync(0xffffffffu, m2, o));
        m3 = fmaxf(m3, __shfl_xor_sync(0xffffffffu, m3, o));
    }
    float s0 = 0.f, s1 = 0.f, s2 = 0.f, s3 = 0.f;
    for (int k = beg + lane; k < end; k += 32) {
        int s = g_eid[k];
        float4 as = *reinterpret_cast<const float4*>(&g_as1[s * 4]);
        float w0 = expf(lrelu(as.x + adv.x) - m0);
        float w1 = expf(lrelu(as.y + adv.y) - m1);
        float w2 = expf(lrelu(as.z + adv.z) - m2);
        float w3 = expf(lrelu(as.w + adv.w) - m3);
        *reinterpret_cast<float4*>(&g_w1[k * 4]) = make_float4(w0, w1, w2, w3);
        s0 += w0; s1 += w1; s2 += w2; s3 += w3;
    }
#pragma unroll
    for (int o = 16; o > 0; o >>= 1) {
        s0 += __shfl_xor_sync(0xffffffffu, s0, o);
        s1 += __shfl_xor_sync(0xffffffffu, s1, o);
        s2 += __shfl_xor_sync(0xffffffffu, s2, o);
        s3 += __shfl_xor_sync(0xffffffffu, s3, o);
    }
    if (lane == 0) {
        *reinterpret_cast<float4*>(&g_inv1[d * 4]) =
            make_float4(1.f / (s0 + 1e-16f), 1.f / (s1 + 1e-16f),
                        1.f / (s2 + 1e-16f), 1.f / (s3 + 1e-16f));
    }
}

// ---------------- layer 1 aggregation: 2 dst/block, fp16 gather, float2 ---------
__global__ void k_agg1(const float* __restrict__ b1) {
    int d = blockIdx.x * 2 + (threadIdx.x >> 7);
    int c2 = threadIdx.x & 127;         // half2 channel pair
    int h = c2 >> 5;                     // head
    int beg = g_off[d], end = g_off[d + 1];
    float ax = 0.f, ay = 0.f;
    int k = beg;
    for (; k + 4 <= end; k += 4) {
        int s0 = g_eid[k], s1 = g_eid[k + 1], s2 = g_eid[k + 2], s3 = g_eid[k + 3];
        float w0 = g_w1[(k + 0) * 4 + h];
        float w1 = g_w1[(k + 1) * 4 + h];
        float w2 = g_w1[(k + 2) * 4 + h];
        float w3 = g_w1[(k + 3) * 4 + h];
        float2 v0 = __half22float2(g_h1h[s0 * 128 + c2]);
        float2 v1 = __half22float2(g_h1h[s1 * 128 + c2]);
        float2 v2 = __half22float2(g_h1h[s2 * 128 + c2]);
        float2 v3 = __half22float2(g_h1h[s3 * 128 + c2]);
        ax += w0 * v0.x + w1 * v1.x + w2 * v2.x + w3 * v3.x;
        ay += w0 * v0.y + w1 * v1.y + w2 * v2.y + w3 * v3.y;
    }
    for (; k < end; k++) {
        float w = g_w1[k * 4 + h];
        float2 v = __half22float2(g_h1h[g_eid[k] * 128 + c2]);
        ax += w * v.x; ay += w * v.y;
    }
    float inv = g_inv1[d * 4 + h];
    float2 bb = reinterpret_cast<const float2*>(b1)[c2];
    float2 o;
    o.x = elu(ax * inv + bb.x);
    o.y = elu(ay * inv + bb.y);
    reinterpret_cast<float2*>(g_o1)[d * 128 + c2] = o;
}

// ---------------- layer 2 GEMM: 64x64 register-tiled, k-chunked ------------------
__global__ void k_gemm2(const float* __restrict__ W2) {
    __shared__ float sA[64 * 68];
    __shared__ float sW[64 * 68];
    int t = threadIdx.x;
    int base = blockIdx.x * 64;
    int oq = t & 15, nq = t >> 4;       // strided tiles: o = oq+16i, n = nq+16j
    float acc[4][4];
#pragma unroll
    for (int j = 0; j < 4; j++)
#pragma unroll
        for (int i = 0; i < 4; i++) acc[j][i] = 0.f;

    const float4* gW = reinterpret_cast<const float4*>(W2);
    const float4* gA = reinterpret_cast<const float4*>(g_o1);
    for (int kc = 0; kc < 4; kc++) {
#pragma unroll
        for (int r = 0; r < 4; r++) {
            int i = r * 256 + t;        // 0..1023 float4 index
            int row = i >> 4;           // 0..63
            int kq = i & 15;            // chunk-local k/4
            *reinterpret_cast<float4*>(&sW[row * 68 + kq * 4]) =
                gW[row * 64 + kc * 16 + kq];
            *reinterpret_cast<float4*>(&sA[row * 68 + kq * 4]) =
                gA[(base + row) * 64 + kc * 16 + kq];
        }
        __syncthreads();
#pragma unroll
        for (int kq = 0; kq < 16; kq++) {
            float4 a[4], b[4];
#pragma unroll
            for (int j = 0; j < 4; j++)
                a[j] = *reinterpret_cast<const float4*>(&sA[(nq + 16 * j) * 68 + kq * 4]);
#pragma unroll
            for (int i = 0; i < 4; i++)
                b[i] = *reinterpret_cast<const float4*>(&sW[(oq + 16 * i) * 68 + kq * 4]);
#pragma unroll
            for (int j = 0; j < 4; j++)
#pragma unroll
                for (int i = 0; i < 4; i++)
                    acc[j][i] += a[j].x * b[i].x + a[j].y * b[i].y
                               + a[j].z * b[i].z + a[j].w * b[i].w;
        }
        __syncthreads();
    }
#pragma unroll
    for (int j = 0; j < 4; j++) {
        int n = base + nq + 16 * j;
#pragma unroll
        for (int i = 0; i < 4; i++)
            g_h2[n * 64 + oq + 16 * i] = acc[j][i];
    }
}

// ---------------- layer 2 attention logits: warp per node ------------------------
__global__ void k_alpha2() {
    __shared__ float s_vs[256], s_vd[256];
    int t = threadIdx.x;
    s_vs[t] = g_v2s[t]; s_vd[t] = g_v2d[t];
    __syncthreads();
    int n = blockIdx.x * 8 + (t >> 5);
    int lane = t & 31;
    const float4* row = reinterpret_cast<const float4*>(g_o1 + n * 256);
    float a = 0.f, b = 0.f;
#pragma unroll
    for (int q = lane; q < 64; q += 32) {
        float4 v = row[q];
        a += v.x * s_vs[q * 4] + v.y * s_vs[q * 4 + 1] + v.z * s_vs[q * 4 + 2] + v.w * s_vs[q * 4 + 3];
        b += v.x * s_vd[q * 4] + v.y * s_vd[q * 4 + 1] + v.z * s_vd[q * 4 + 2] + v.w * s_vd[q * 4 + 3];
    }
#pragma unroll
    for (int o = 16; o > 0; o >>= 1) {
        a += __shfl_xor_sync(0xffffffffu, a, o);
        b += __shfl_xor_sync(0xffffffffu, b, o);
    }
    if (lane == 0) { g_as2[n] = a; g_ad2[n] = b; }
}

// ---------------- layer 2 softmax weights: warp per dst --------------------------
__global__ void k_w2() {
    int d = blockIdx.x * 4 + (threadIdx.x >> 5);
    if (d >= NN) return;
    int lane = threadIdx.x & 31;
    int beg = g_off[d], end = g_off[d + 1];
    float ad = g_ad2[d];
    float m = NEG_INF;
    for (int k = beg + lane; k < end; k += 32)
        m = fmaxf(m, lrelu(g_as2[g_eid[k]] + ad));
#pragma unroll
    for (int o = 16; o > 0; o >>= 1) m = fmaxf(m, __shfl_xor_sync(0xffffffffu, m, o));
    float ssum = 0.f;
    for (int k = beg + lane; k < end; k += 32) {
        float w = expf(lrelu(g_as2[g_eid[k]] + ad) - m);
        g_w2[k] = w;
        ssum += w;
    }
#pragma unroll
    for (int o = 16; o > 0; o >>= 1) ssum += __shfl_xor_sync(0xffffffffu, ssum, o);
    if (lane == 0) g_inv2[d] = 1.f / (ssum + 1e-16f);
}

// ---------------- layer 2 aggregation: 8 dst/block, float2 gather ----------------
__global__ void k_agg2(const float* __restrict__ b2) {
    int d = blockIdx.x * 8 + (threadIdx.x >> 5);
    int c2 = threadIdx.x & 31;
    int beg = g_off[d], end = g_off[d + 1];
    const float2* h2v = reinterpret_cast<const float2*>(g_h2);
    float ax = 0.f, ay = 0.f;
    int k = beg;
    for (; k + 4 <= end; k += 4) {
        int s0 = g_eid[k], s1 = g_eid[k + 1], s2 = g_eid[k + 2], s3 = g_eid[k + 3];
        float w0 = g_w2[k], w1 = g_w2[k + 1], w2 = g_w2[k + 2], w3 = g_w2[k + 3];
        float2 v0 = h2v[s0 * 32 + c2];
        float2 v1 = h2v[s1 * 32 + c2];
        float2 v2 = h2v[s2 * 32 + c2];
        float2 v3 = h2v[s3 * 32 + c2];
        ax += w0 * v0.x + w1 * v1.x + w2 * v2.x + w3 * v3.x;
        ay += w0 * v0.y + w1 * v1.y + w2 * v2.y + w3 * v3.y;
    }
    for (; k < end; k++) {
        float w = g_w2[k];
        float2 v = h2v[g_eid[k] * 32 + c2];
        ax += w * v.x; ay += w * v.y;
    }
    float inv = g_inv2[d];
    float2 bb = reinterpret_cast<const float2*>(b2)[c2];
    float2 o;
    o.x = elu(ax * inv + bb.x);
    o.y = elu(ay * inv + bb.y);
    reinterpret_cast<float2*>(g_o2)[d * 32 + c2] = o;
}

// ---------------- final projection (64 -> 1) -------------------------------------
__global__ void k_final(const float* __restrict__ fw, const float* __restrict__ fb,
                        float* __restrict__ out) {
    int g = blockIdx.x * blockDim.x + threadIdx.x;
    int n = g >> 5, lane = g & 31;
    if (n >= NN) return;
    float v = g_o2[n * 64 + lane] * fw[lane] + g_o2[n * 64 + 32 + lane] * fw[32 + lane];
#pragma unroll
    for (int s = 16; s > 0; s >>= 1) v += __shfl_down_sync(0xffffffffu, v, s);
    if (lane == 0) out[n] = v + fb[0];
}

// ---------------- launch -----------------------------------------------------------
extern "C" void kernel_launch(void* const* d_in, const int* in_sizes, int n_in,
                              void* d_out, int out_size) {
    const float* x   = (const float*)d_in[0];
    const int*   ei  = (const int*)d_in[1];
    const float* W1  = (const float*)d_in[2];
    const float* as1 = (const float*)d_in[3];
    const float* ad1 = (const float*)d_in[4];
    const float* b1  = (const float*)d_in[5];
    const float* W2  = (const float*)d_in[6];
    const float* as2 = (const float*)d_in[7];
    const float* ad2 = (const float*)d_in[8];
    const float* b2  = (const float*)d_in[9];
    const float* fw  = (const float*)d_in[10];
    const float* fb  = (const float*)d_in[11];
    float*       out = (float*)d_out;

    k_detect<<<1, 32>>>(ei);
    k_zero<<<NPART, 256>>>();
    k_convert<<<(ET + 255) / 256, 256>>>(ei);
    k_scan_part<<<NPART, 256>>>();
    k_scan_mid<<<1, 256>>>();
    k_scan_fin<<<NPART, 256>>>();
    k_scatter<<<(ET + 255) / 256, 256>>>();
    k_prew<<<1, 256>>>(W1, as1, ad1, W2, as2, ad2);
    k_gemm1<<<NN / 8, 256>>>(x, W1);
    k_alpha1<<<(NN + 63) / 64, 64>>>(x);
    k_w1<<<(NN + 3) / 4, 128>>>();
    k_agg1<<<NN / 2, 256>>>(b1);
    k_gemm2<<<NN2 / 64, 256>>>(W2);
    k_alpha2<<<NN / 8, 256>>>();
    k_w2<<<(NN + 3) / 4, 128>>>();
    k_agg2<<<NN / 8, 256>>>(b2);
    k_final<<<(NN * 32 + 255) / 256, 256>>>(fw, fb, out);
}

// round 8
// speedup vs baseline: 5.4764x; 1.1220x over previous
#include <cuda_runtime.h>
#include <cuda_fp16.h>
#include <stdint.h>
#include <math.h>

#define NN 50000
#define NN2 50048          // padded to multiple of 64 for gemm2 tiles
#define FE 800000
#define ET (FE + NN)
#define NPART 196          // ceil(NN/256)
#define CH1 256
#define CH2 256

// ---------------- scratch ----------------------------------------------------
__device__ __half2 g_h1h[NN * 128];    // layer1 features fp16 (gather-only)
__device__ __half2 g_o1h[NN2 * 128];   // elu(layer1 out) fp16 (gemm2 A / alpha2)
__device__ float   g_as1[NN * 4];
__device__ float   g_ad1[NN * 4];
__device__ __half  g_W2h[64 * 256];    // W2 fp16
__device__ __half2 g_h2h[NN2 * 32];    // layer2 pre-agg features fp16
__device__ float   g_o2[NN * 64];
__device__ float   g_as2[NN];
__device__ float   g_ad2[NN];
__device__ int     g_eid[ET];
__device__ int     g_cnt[NN];
__device__ int     g_off[NN + 1];
__device__ int     g_cur[NN];
__device__ int     g_part[256];
__device__ int     g_partx[256];
__device__ int     g_is64;
__device__ float   g_ws1s[64];
__device__ float   g_ws1d[64];
__device__ float   g_v2s[256];
__device__ float   g_v2d[256];
__device__ int     g_srcb[ET];
__device__ int     g_dstb[ET];

__device__ __forceinline__ float lrelu(float v) { return v > 0.f ? v : 0.2f * v; }
__device__ __forceinline__ float elu(float v)   { return v > 0.f ? v : expm1f(v); }
__device__ __forceinline__ uint32_t su32(const void* p) {
    return (uint32_t)__cvta_generic_to_shared(p);
}
#define NEG_INF __int_as_float(0xff800000)

// ---------------- init: zero degree counters + dtype detect --------------------
__global__ void k_init(const int* __restrict__ ei32) {
    int i = blockIdx.x * blockDim.x + threadIdx.x;
    if (i < NN) g_cnt[i] = 0;
    if (blockIdx.x == 0) {
        int nz = 0;
        for (int k = threadIdx.x; k < 1024; k += 256) nz |= ei32[2 * k + 1];
        int any = __syncthreads_or(nz);
        if (threadIdx.x == 0) g_is64 = (any == 0);
    }
}
__global__ void k_convert(const int* __restrict__ ei32) {
    int i = blockIdx.x * blockDim.x + threadIdx.x;
    if (i >= ET) return;
    int s, d;
    if (i < FE) {
        if (g_is64) { s = ei32[2 * i]; d = ei32[2 * (FE + i)]; }
        else        { s = ei32[i];     d = ei32[FE + i]; }
    } else { s = i - FE; d = s; }
    g_srcb[i] = s; g_dstb[i] = d;
    atomicAdd(&g_cnt[d], 1);
}

// ---------------- scan (CSR offsets) --------------------------------------------
__global__ void k_scan_part() {
    __shared__ int sm[256];
    int b = blockIdx.x, t = threadIdx.x, i = b * 256 + t;
    sm[t] = (i < NN) ? g_cnt[i] : 0;
    __syncthreads();
#pragma unroll
    for (int s = 128; s > 0; s >>= 1) { if (t < s) sm[t] += sm[t + s]; __syncthreads(); }
    if (t == 0) g_part[b] = sm[0];
}
__global__ void k_scan_mid() {
    __shared__ int sm[256];
    int t = threadIdx.x;
    int v = (t < NPART) ? g_part[t] : 0;
    sm[t] = v; __syncthreads();
#pragma unroll
    for (int s = 1; s < 256; s <<= 1) {
        int a = (t >= s) ? sm[t - s] : 0;
        __syncthreads(); sm[t] += a; __syncthreads();
    }
    g_partx[t] = sm[t] - v;
    if (t == 0) g_off[NN] = ET;
}
__global__ void k_scan_fin() {
    __shared__ int sm[256];
    int b = blockIdx.x, t = threadIdx.x, i = b * 256 + t;
    int v = (i < NN) ? g_cnt[i] : 0;
    sm[t] = v; __syncthreads();
#pragma unroll
    for (int s = 1; s < 256; s <<= 1) {
        int a = (t >= s) ? sm[t - s] : 0;
        __syncthreads(); sm[t] += a; __syncthreads();
    }
    if (i < NN) {
        int off = g_partx[b] + sm[t] - v;
        g_off[i] = off; g_cur[i] = off;
    }
}
__global__ void k_scatter() {
    int i = blockIdx.x * blockDim.x + threadIdx.x;
    if (i >= ET) return;
    int d = g_dstb[i];
    int pos = atomicAdd(&g_cur[d], 1);
    g_eid[pos] = g_srcb[i];
}

// ---------------- fold attention vectors + W2 -> fp16 ----------------------------
__global__ void k_prew(const float* __restrict__ W1,
                       const float* __restrict__ as1, const float* __restrict__ ad1,
                       const float* __restrict__ W2,
                       const float* __restrict__ as2, const float* __restrict__ ad2) {
    int t = threadIdx.x;
    if (t < 64) {
        int h = t >> 4, i = t & 15;
        float s = 0.f, d = 0.f;
        for (int c = 0; c < 64; c++) {
            float w = W1[(h * 64 + c) * 16 + i];
            s += as1[h * 64 + c] * w;
            d += ad1[h * 64 + c] * w;
        }
        g_ws1s[t] = s; g_ws1d[t] = d;
    }
    {
        float s = 0.f, d = 0.f;
        for (int o = 0; o < 64; o++) {
            float w = W2[o * 256 + t];
            s += as2[o] * w;
            d += ad2[o] * w;
        }
        g_v2s[t] = s; g_v2d[t] = d;
    }
    for (int j = 0; j < 64; j++) {
        int idx = j * 256 + t;
        g_W2h[idx] = __float2half(W2[idx]);
    }
}

// ---------------- layer 1 GEMM: 8 nodes / block, fp16 output ---------------------
__global__ void k_gemm1(const float* __restrict__ x, const float* __restrict__ W1) {
    __shared__ float xs[128];
    int t = threadIdx.x, b = blockIdx.x;
    if (t < 128) xs[t] = x[b * 128 + t];
    __syncthreads();
    const float4* W4 = reinterpret_cast<const float4*>(W1) + t * 4;
    float4 w0 = W4[0], w1 = W4[1], w2 = W4[2], w3 = W4[3];
#pragma unroll
    for (int j = 0; j < 8; j++) {
        const float* xv = xs + j * 16;
        float acc = xv[0] * w0.x + xv[1] * w0.y + xv[2] * w0.z + xv[3] * w0.w
                  + xv[4] * w1.x + xv[5] * w1.y + xv[6] * w1.z + xv[7] * w1.w
                  + xv[8] * w2.x + xv[9] * w2.y + xv[10] * w2.z + xv[11] * w2.w
                  + xv[12] * w3.x + xv[13] * w3.y + xv[14] * w3.z + xv[15] * w3.w;
        float hi = __shfl_down_sync(0xffffffffu, acc, 1);
        if (!(t & 1)) g_h1h[(b * 8 + j) * 128 + (t >> 1)] = __floats2half2_rn(acc, hi);
    }
}

// ---------------- layer 1 attention logits ---------------------------------------
__global__ void k_alpha1(const float* __restrict__ x) {
    __shared__ float ws[64], wd[64];
    int t = threadIdx.x;
    if (t < 64) { ws[t] = g_ws1s[t]; wd[t] = g_ws1d[t]; }
    __syncthreads();
    int n = blockIdx.x * blockDim.x + t;
    if (n >= NN) return;
    const float4* xv = reinterpret_cast<const float4*>(x + n * 16);
    float4 x0 = xv[0], x1 = xv[1], x2 = xv[2], x3 = xv[3];
#pragma unroll
    for (int h = 0; h < 4; h++) {
        const float* s = ws + h * 16;
        const float* d = wd + h * 16;
        float a = x0.x * s[0] + x0.y * s[1] + x0.z * s[2] + x0.w * s[3]
                + x1.x * s[4] + x1.y * s[5] + x1.z * s[6] + x1.w * s[7]
                + x2.x * s[8] + x2.y * s[9] + x2.z * s[10] + x2.w * s[11]
                + x3.x * s[12] + x3.y * s[13] + x3.z * s[14] + x3.w * s[15];
        float b = x0.x * d[0] + x0.y * d[1] + x0.z * d[2] + x0.w * d[3]
                + x1.x * d[4] + x1.y * d[5] + x1.z * d[6] + x1.w * d[7]
                + x2.x * d[8] + x2.y * d[9] + x2.z * d[10] + x2.w * d[11]
                + x3.x * d[12] + x3.y * d[13] + x3.z * d[14] + x3.w * d[15];
        g_as1[n * 4 + h] = a;
        g_ad1[n * 4 + h] = b;
    }
}

// ---------------- layer 1 FUSED softmax + aggregate (block per dst) ---------------
__global__ void k_fagg1(const float* __restrict__ b1) {
    __shared__ float sw[4][CH1];
    __shared__ int   si[CH1];
    __shared__ float sred[4][8];
    __shared__ float gm[4], gs[4], gf[4], cf[4];
    int d = blockIdx.x;
    int t = threadIdx.x;              // 128
    int lane = t & 31, warp = t >> 5;
    int beg = g_off[d], end = g_off[d + 1];
    int c2 = t, h = t >> 5;
    float4 adv = *reinterpret_cast<const float4*>(&g_ad1[d * 4]);
    if (t < 4) { gm[t] = NEG_INF; gs[t] = 0.f; }
    float ax = 0.f, ay = 0.f;
    for (int cb = beg; cb < end; cb += CH1) {
        int cnt = min(end - cb, CH1);
        // phase 1: logits + chunk max
        float m0 = NEG_INF, m1 = NEG_INF, m2 = NEG_INF, m3 = NEG_INF;
        for (int e = t; e < cnt; e += 128) {
            int s = g_eid[cb + e];
            si[e] = s;
            float4 as = *reinterpret_cast<const float4*>(&g_as1[s * 4]);
            float e0 = lrelu(as.x + adv.x), e1 = lrelu(as.y + adv.y);
            float e2 = lrelu(as.z + adv.z), e3 = lrelu(as.w + adv.w);
            sw[0][e] = e0; sw[1][e] = e1; sw[2][e] = e2; sw[3][e] = e3;
            m0 = fmaxf(m0, e0); m1 = fmaxf(m1, e1);
            m2 = fmaxf(m2, e2); m3 = fmaxf(m3, e3);
        }
#pragma unroll
        for (int o = 16; o > 0; o >>= 1) {
            m0 = fmaxf(m0, __shfl_xor_sync(0xffffffffu, m0, o));
            m1 = fmaxf(m1, __shfl_xor_sync(0xffffffffu, m1, o));
            m2 = fmaxf(m2, __shfl_xor_sync(0xffffffffu, m2, o));
            m3 = fmaxf(m3, __shfl_xor_sync(0xffffffffu, m3, o));
        }
        if (lane == 0) { sred[0][warp] = m0; sred[1][warp] = m1; sred[2][warp] = m2; sred[3][warp] = m3; }
        __syncthreads();
        if (t < 4) {
            float cm = fmaxf(fmaxf(sred[t][0], sred[t][1]), fmaxf(sred[t][2], sred[t][3]));
            sred[t][4] = cm;
        }
        __syncthreads();
        // phase 2: exp + chunk sums
        float cm0 = sred[0][4], cm1 = sred[1][4], cm2 = sred[2][4], cm3 = sred[3][4];
        float s0 = 0.f, s1 = 0.f, s2 = 0.f, s3 = 0.f;
        for (int e = t; e < cnt; e += 128) {
            float w0 = __expf(sw[0][e] - cm0); sw[0][e] = w0; s0 += w0;
            float w1 = __expf(sw[1][e] - cm1); sw[1][e] = w1; s1 += w1;
            float w2 = __expf(sw[2][e] - cm2); sw[2][e] = w2; s2 += w2;
            float w3 = __expf(sw[3][e] - cm3); sw[3][e] = w3; s3 += w3;
        }
#pragma unroll
        for (int o = 16; o > 0; o >>= 1) {
            s0 += __shfl_xor_sync(0xffffffffu, s0, o);
            s1 += __shfl_xor_sync(0xffffffffu, s1, o);
            s2 += __shfl_xor_sync(0xffffffffu, s2, o);
            s3 += __shfl_xor_sync(0xffffffffu, s3, o);
        }
        __syncthreads();   // sred[*][4] consumed; safe to overwrite 0..3
        if (lane == 0) { sred[0][warp] = s0; sred[1][warp] = s1; sred[2][warp] = s2; sred[3][warp] = s3; }
        __syncthreads();
        if (t < 4) {
            float cs = sred[t][0] + sred[t][1] + sred[t][2] + sred[t][3];
            float cm = sred[t][4];
            float nm = fmaxf(gm[t], cm);
            float f = __expf(gm[t] - nm);
            float c = __expf(cm - nm);
            gs[t] = gs[t] * f + cs * c;
            gm[t] = nm;
            gf[t] = f; cf[t] = c;
        }
        __syncthreads();
        // phase 3: weighted gather for this chunk
        float cax = 0.f, cay = 0.f;
        const float* swh = sw[h];
        int e = 0;
        for (; e + 4 <= cnt; e += 4) {
            int i0 = si[e], i1 = si[e + 1], i2 = si[e + 2], i3 = si[e + 3];
            float w0 = swh[e], w1 = swh[e + 1], w2 = swh[e + 2], w3 = swh[e + 3];
            float2 v0 = __half22float2(g_h1h[i0 * 128 + c2]);
            float2 v1 = __half22float2(g_h1h[i1 * 128 + c2]);
            float2 v2 = __half22float2(g_h1h[i2 * 128 + c2]);
            float2 v3 = __half22float2(g_h1h[i3 * 128 + c2]);
            cax += w0 * v0.x + w1 * v1.x + w2 * v2.x + w3 * v3.x;
            cay += w0 * v0.y + w1 * v1.y + w2 * v2.y + w3 * v3.y;
        }
        for (; e < cnt; e++) {
            float w = swh[e];
            float2 v = __half22float2(g_h1h[si[e] * 128 + c2]);
            cax += w * v.x; cay += w * v.y;
        }
        ax = ax * gf[h] + cax * cf[h];
        ay = ay * gf[h] + cay * cf[h];
        __syncthreads();
    }
    float inv = 1.f / (gs[h] + 1e-16f);
    float2 bb = reinterpret_cast<const float2*>(b1)[c2];
    float ox = elu(ax * inv + bb.x);
    float oy = elu(ay * inv + bb.y);
    g_o1h[d * 128 + c2] = __floats2half2_rn(ox, oy);
}

// ---------------- layer 2 GEMM: tensor cores (mma.sync m16n8k16 f16) --------------
#define MMA16816(C, A0, A1, A2, A3, B0, B1)                                   \
    asm volatile("mma.sync.aligned.m16n8k16.row.col.f32.f16.f16.f32 "          \
        "{%0,%1,%2,%3}, {%4,%5,%6,%7}, {%8,%9}, {%0,%1,%2,%3};"                \
        : "+f"(C[0]), "+f"(C[1]), "+f"(C[2]), "+f"(C[3])                       \
        : "r"(A0), "r"(A1), "r"(A2), "r"(A3), "r"(B0), "r"(B1))

__global__ void k_gemm2() {
    __shared__ __align__(16) __half sA[64 * 256];
    __shared__ __align__(16) __half sW[64 * 256];
    int t = threadIdx.x;               // 128
    int base = blockIdx.x * 64;
    const uint4* gA = reinterpret_cast<const uint4*>(g_o1h) + base * 32;
    const uint4* gW = reinterpret_cast<const uint4*>(g_W2h);
#pragma unroll
    for (int j = 0; j < 16; j++) {
        int i = j * 128 + t;
        int r = i >> 5, c = i & 31;
        int sc = c ^ (r & 7);
        *reinterpret_cast<uint4*>(&sA[r * 256 + sc * 8]) = gA[i];
        *reinterpret_cast<uint4*>(&sW[r * 256 + sc * 8]) = gW[i];
    }
    __syncthreads();
    int lane = t & 31, warp = t >> 5;
    int m0 = warp * 16;
    float acc[8][4];
#pragma unroll
    for (int i = 0; i < 8; i++)
#pragma unroll
        for (int j = 0; j < 4; j++) acc[i][j] = 0.f;

    int arow = m0 + (lane & 7) + ((lane >> 3) & 1) * 8;
    int akc  = (lane >> 4);                       // 0/1 extra 16B chunk
    int brin = ((lane >> 4) & 1) * 8 + (lane & 7);
    int bkc  = (lane >> 3) & 1;
#pragma unroll
    for (int kt = 0; kt < 16; kt++) {
        int ac = kt * 2 + akc;
        uint32_t aaddr = su32(&sA[arow * 256 + ((ac ^ (arow & 7)) << 3)]);
        uint32_t a0, a1, a2, a3;
        asm volatile("ldmatrix.sync.aligned.m8n8.x4.shared.b16 {%0,%1,%2,%3}, [%4];"
            : "=r"(a0), "=r"(a1), "=r"(a2), "=r"(a3) : "r"(aaddr));
#pragma unroll
        for (int og = 0; og < 4; og++) {
            int brow = og * 16 + brin;
            int bc = kt * 2 + bkc;
            uint32_t baddr = su32(&sW[brow * 256 + ((bc ^ (brow & 7)) << 3)]);
            uint32_t b0, b1, b2, b3;
            // W2 is [o][k] row-major = K x N col-major: NO .trans for the B fragment
            asm volatile("ldmatrix.sync.aligned.m8n8.x4.shared.b16 {%0,%1,%2,%3}, [%4];"
                : "=r"(b0), "=r"(b1), "=r"(b2), "=r"(b3) : "r"(baddr));
            MMA16816(acc[og * 2],     a0, a1, a2, a3, b0, b1);
            MMA16816(acc[og * 2 + 1], a0, a1, a2, a3, b2, b3);
        }
    }
    int r0 = base + m0 + (lane >> 2);
    int cq = lane & 3;
#pragma unroll
    for (int ot = 0; ot < 8; ot++) {
        g_h2h[r0 * 32 + ot * 4 + cq]       = __floats2half2_rn(acc[ot][0], acc[ot][1]);
        g_h2h[(r0 + 8) * 32 + ot * 4 + cq] = __floats2half2_rn(acc[ot][2], acc[ot][3]);
    }
}

// ---------------- layer 2 attention logits (warp per node, fp16 input) -------------
__global__ void k_alpha2() {
    __shared__ float s_vs[256], s_vd[256];
    int t = threadIdx.x;
    s_vs[t] = g_v2s[t]; s_vd[t] = g_v2d[t];
    __syncthreads();
    int n = blockIdx.x * 8 + (t >> 5);
    int lane = t & 31;
    uint4 raw = reinterpret_cast<const uint4*>(g_o1h)[n * 32 + lane];
    const __half2* hp = reinterpret_cast<const __half2*>(&raw);
    int kb = lane * 8;
    float a = 0.f, b = 0.f;
#pragma unroll
    for (int j = 0; j < 4; j++) {
        float2 f = __half22float2(hp[j]);
        a += f.x * s_vs[kb + 2 * j] + f.y * s_vs[kb + 2 * j + 1];
        b += f.x * s_vd[kb + 2 * j] + f.y * s_vd[kb + 2 * j + 1];
    }
#pragma unroll
    for (int o = 16; o > 0; o >>= 1) {
        a += __shfl_xor_sync(0xffffffffu, a, o);
        b += __shfl_xor_sync(0xffffffffu, b, o);
    }
    if (lane == 0) { g_as2[n] = a; g_ad2[n] = b; }
}

// ---------------- layer 2 FUSED softmax + aggregate (warp per dst) ------------------
__global__ void k_fagg2(const float* __restrict__ b2) {
    __shared__ float sw[8][CH2];
    __shared__ int   si[8][CH2];
    int wid = threadIdx.x >> 5, lane = threadIdx.x & 31;
    int d = blockIdx.x * 8 + wid;
    int beg = g_off[d], end = g_off[d + 1];
    float ad = g_ad2[d];
    float gmv = NEG_INF, gsv = 0.f, ax = 0.f, ay = 0.f;
    for (int cb = beg; cb < end; cb += CH2) {
        int cnt = min(end - cb, CH2);
        float m = NEG_INF;
        for (int e = lane; e < cnt; e += 32) {
            int s = g_eid[cb + e];
            si[wid][e] = s;
            float lg = lrelu(g_as2[s] + ad);
            sw[wid][e] = lg;
            m = fmaxf(m, lg);
        }
#pragma unroll
        for (int o = 16; o > 0; o >>= 1) m = fmaxf(m, __shfl_xor_sync(0xffffffffu, m, o));
        float ssum = 0.f;
        for (int e = lane; e < cnt; e += 32) {
            float w = __expf(sw[wid][e] - m);
            sw[wid][e] = w;
            ssum += w;
        }
#pragma unroll
        for (int o = 16; o > 0; o >>= 1) ssum += __shfl_xor_sync(0xffffffffu, ssum, o);
        __syncwarp();
        float cax = 0.f, cay = 0.f;
        const float* swh = sw[wid];
        const int* sih = si[wid];
        int e = 0;
        for (; e + 4 <= cnt; e += 4) {
            int i0 = sih[e], i1 = sih[e + 1], i2 = sih[e + 2], i3 = sih[e + 3];
            float w0 = swh[e], w1 = swh[e + 1], w2 = swh[e + 2], w3 = swh[e + 3];
            float2 v0 = __half22float2(g_h2h[i0 * 32 + lane]);
            float2 v1 = __half22float2(g_h2h[i1 * 32 + lane]);
            float2 v2 = __half22float2(g_h2h[i2 * 32 + lane]);
            float2 v3 = __half22float2(g_h2h[i3 * 32 + lane]);
            cax += w0 * v0.x + w1 * v1.x + w2 * v2.x + w3 * v3.x;
            cay += w0 * v0.y + w1 * v1.y + w2 * v2.y + w3 * v3.y;
        }
        for (; e < cnt; e++) {
            float w = swh[e];
            float2 v = __half22float2(g_h2h[sih[e] * 32 + lane]);
            cax += w * v.x; cay += w * v.y;
        }
        float nm = fmaxf(gmv, m);
        float f = __expf(gmv - nm), c = __expf(m - nm);
        gsv = gsv * f + ssum * c;
        ax = ax * f + cax * c;
        ay = ay * f + cay * c;
        gmv = nm;
        __syncwarp();
    }
    float inv = 1.f / (gsv + 1e-16f);
    float2 bb = reinterpret_cast<const float2*>(b2)[lane];
    float2 o;
    o.x = elu(ax * inv + bb.x);
    o.y = elu(ay * inv + bb.y);
    reinterpret_cast<float2*>(g_o2)[d * 32 + lane] = o;
}

// ---------------- final projection (64 -> 1) ----------------------------------------
__global__ void k_final(const float* __restrict__ fw, const float* __restrict__ fb,
                        float* __restrict__ out) {
    int g = blockIdx.x * blockDim.x + threadIdx.x;
    int n = g >> 5, lane = g & 31;
    if (n >= NN) return;
    float v = g_o2[n * 64 + lane] * fw[lane] + g_o2[n * 64 + 32 + lane] * fw[32 + lane];
#pragma unroll
    for (int s = 16; s > 0; s >>= 1) v += __shfl_down_sync(0xffffffffu, v, s);
    if (lane == 0) out[n] = v + fb[0];
}

// ---------------- launch --------------------------------------------------------------
extern "C" void kernel_launch(void* const* d_in, const int* in_sizes, int n_in,
                              void* d_out, int out_size) {
    const float* x   = (const float*)d_in[0];
    const int*   ei  = (const int*)d_in[1];
    const float* W1  = (const float*)d_in[2];
    const float* as1 = (const float*)d_in[3];
    const float* ad1 = (const float*)d_in[4];
    const float* b1  = (const float*)d_in[5];
    const float* W2  = (const float*)d_in[6];
    const float* as2 = (const float*)d_in[7];
    const float* ad2 = (const float*)d_in[8];
    const float* b2  = (const float*)d_in[9];
    const float* fw  = (const float*)d_in[10];
    const float* fb  = (const float*)d_in[11];
    float*       out = (float*)d_out;

    k_init<<<NPART, 256>>>(ei);
    k_convert<<<(ET + 255) / 256, 256>>>(ei);
    k_scan_part<<<NPART, 256>>>();
    k_scan_mid<<<1, 256>>>();
    k_scan_fin<<<NPART, 256>>>();
    k_scatter<<<(ET + 255) / 256, 256>>>();
    k_prew<<<1, 256>>>(W1, as1, ad1, W2, as2, ad2);
    k_gemm1<<<NN / 8, 256>>>(x, W1);
    k_alpha1<<<(NN + 63) / 64, 64>>>(x);
    k_fagg1<<<NN, 128>>>(b1);
    k_gemm2<<<NN2 / 64, 128>>>();
    k_alpha2<<<NN / 8, 256>>>();
    k_fagg2<<<NN / 8, 256>>>(b2);
    k_final<<<(NN * 32 + 255) / 256, 256>>>(fw, fb, out);
}

// round 9
// speedup vs baseline: 6.2640x; 1.1438x over previous
#include <cuda_runtime.h>
#include <cuda_fp16.h>
#include <stdint.h>
#include <math.h>

#define NN 50000
#define NN2 50048          // padded to multiple of 64 for gemm2 tiles
#define FE 800000
#define ET (FE + NN)
#define NPART 196          // ceil(NN/256)
#define CH1 256
#define CH2 256

// ---------------- scratch ----------------------------------------------------
__device__ __half2 g_h1h[NN * 128];    // layer1 features fp16 (gather-only)
__device__ __half2 g_o1h[NN2 * 128];   // elu(layer1 out) fp16 (gemm2 A)
__device__ float   g_as1[NN * 4];
__device__ float   g_ad1[NN * 4];
__device__ __half  g_W2h[64 * 256];    // W2 fp16
__device__ __half2 g_h2h[NN2 * 32];    // layer2 pre-agg features fp16
__device__ float   g_o2[NN * 64];
__device__ float   g_as2[NN];
__device__ float   g_ad2[NN];
__device__ int     g_eid[ET];
__device__ int     g_cnt[NN];
__device__ int     g_off[NN + 1];
__device__ int     g_cur[NN];
__device__ int     g_part[256];
__device__ int     g_partx[256];
__device__ int     g_is64;
__device__ float   g_ws1s[64];
__device__ float   g_ws1d[64];
__device__ float   g_v2s[256];
__device__ float   g_v2d[256];

__device__ __forceinline__ float lrelu(float v) { return v > 0.f ? v : 0.2f * v; }
__device__ __forceinline__ float elu(float v)   { return v > 0.f ? v : expm1f(v); }
__device__ __forceinline__ uint32_t su32(const void* p) {
    return (uint32_t)__cvta_generic_to_shared(p);
}
#define NEG_INF __int_as_float(0xff800000)

// ---------------- init: zero degree counters + dtype detect --------------------
__global__ void k_init(const int* __restrict__ ei32) {
    int i = blockIdx.x * blockDim.x + threadIdx.x;
    if (i < NN) g_cnt[i] = 0;
    if (blockIdx.x == 0) {
        int nz = 0;
        for (int k = threadIdx.x; k < 1024; k += 256) nz |= ei32[2 * k + 1];
        int any = __syncthreads_or(nz);
        if (threadIdx.x == 0) g_is64 = (any == 0);
    }
}
// count in-degrees (src/dst recomputed later in scatter; no intermediate buffers)
__global__ void k_convert(const int* __restrict__ ei32) {
    int i = blockIdx.x * blockDim.x + threadIdx.x;
    if (i >= ET) return;
    int d;
    if (i < FE) d = g_is64 ? ei32[2 * (FE + i)] : ei32[FE + i];
    else        d = i - FE;
    atomicAdd(&g_cnt[d], 1);
}

// ---------------- scan (CSR offsets) --------------------------------------------
__global__ void k_scan_part() {
    __shared__ int sm[256];
    int b = blockIdx.x, t = threadIdx.x, i = b * 256 + t;
    sm[t] = (i < NN) ? g_cnt[i] : 0;
    __syncthreads();
#pragma unroll
    for (int s = 128; s > 0; s >>= 1) { if (t < s) sm[t] += sm[t + s]; __syncthreads(); }
    if (t == 0) g_part[b] = sm[0];
}
__global__ void k_scan_mid() {
    __shared__ int sm[256];
    int t = threadIdx.x;
    int v = (t < NPART) ? g_part[t] : 0;
    sm[t] = v; __syncthreads();
#pragma unroll
    for (int s = 1; s < 256; s <<= 1) {
        int a = (t >= s) ? sm[t - s] : 0;
        __syncthreads(); sm[t] += a; __syncthreads();
    }
    g_partx[t] = sm[t] - v;
    if (t == 0) g_off[NN] = ET;
}
__global__ void k_scan_fin() {
    __shared__ int sm[256];
    int b = blockIdx.x, t = threadIdx.x, i = b * 256 + t;
    int v = (i < NN) ? g_cnt[i] : 0;
    sm[t] = v; __syncthreads();
#pragma unroll
    for (int s = 1; s < 256; s <<= 1) {
        int a = (t >= s) ? sm[t - s] : 0;
        __syncthreads(); sm[t] += a; __syncthreads();
    }
    if (i < NN) {
        int off = g_partx[b] + sm[t] - v;
        g_off[i] = off; g_cur[i] = off;
    }
}
__global__ void k_scatter(const int* __restrict__ ei32) {
    int i = blockIdx.x * blockDim.x + threadIdx.x;
    if (i >= ET) return;
    int s, d;
    if (i < FE) {
        if (g_is64) { s = ei32[2 * i]; d = ei32[2 * (FE + i)]; }
        else        { s = ei32[i];     d = ei32[FE + i]; }
    } else { s = i - FE; d = s; }
    int pos = atomicAdd(&g_cur[d], 1);
    g_eid[pos] = s;
}

// ---------------- fold attention vectors + W2 -> fp16 ----------------------------
__global__ void k_prew(const float* __restrict__ W1,
                       const float* __restrict__ as1, const float* __restrict__ ad1,
                       const float* __restrict__ W2,
                       const float* __restrict__ as2, const float* __restrict__ ad2) {
    int t = threadIdx.x;
    if (t < 64) {
        int h = t >> 4, i = t & 15;
        float s = 0.f, d = 0.f;
        for (int c = 0; c < 64; c++) {
            float w = W1[(h * 64 + c) * 16 + i];
            s += as1[h * 64 + c] * w;
            d += ad1[h * 64 + c] * w;
        }
        g_ws1s[t] = s; g_ws1d[t] = d;
    }
    {
        float s = 0.f, d = 0.f;
        for (int o = 0; o < 64; o++) {
            float w = W2[o * 256 + t];
            s += as2[o] * w;
            d += ad2[o] * w;
        }
        g_v2s[t] = s; g_v2d[t] = d;
    }
    for (int j = 0; j < 64; j++) {
        int idx = j * 256 + t;
        g_W2h[idx] = __float2half(W2[idx]);
    }
}

// ---------------- layer 1 GEMM (8 nodes/block) + fused attention logits ----------
__global__ void k_gemm1(const float* __restrict__ x, const float* __restrict__ W1) {
    __shared__ float xs[128];
    int t = threadIdx.x, b = blockIdx.x;
    if (t < 128) xs[t] = x[b * 128 + t];
    __syncthreads();
    if (t < 64) {   // logits: 8 nodes x 4 heads x {src,dst}
        int j = t >> 3, h = (t >> 1) & 3, sd = t & 1;
        const float* wv = (sd ? g_ws1d : g_ws1s) + h * 16;
        const float* xv = xs + j * 16;
        float a = 0.f;
#pragma unroll
        for (int i = 0; i < 16; i++) a += xv[i] * wv[i];
        int n = b * 8 + j;
        if (sd) g_ad1[n * 4 + h] = a; else g_as1[n * 4 + h] = a;
    }
    const float4* W4 = reinterpret_cast<const float4*>(W1) + t * 4;
    float4 w0 = W4[0], w1 = W4[1], w2 = W4[2], w3 = W4[3];
#pragma unroll
    for (int j = 0; j < 8; j++) {
        const float* xv = xs + j * 16;
        float acc = xv[0] * w0.x + xv[1] * w0.y + xv[2] * w0.z + xv[3] * w0.w
                  + xv[4] * w1.x + xv[5] * w1.y + xv[6] * w1.z + xv[7] * w1.w
                  + xv[8] * w2.x + xv[9] * w2.y + xv[10] * w2.z + xv[11] * w2.w
                  + xv[12] * w3.x + xv[13] * w3.y + xv[14] * w3.z + xv[15] * w3.w;
        float hi = __shfl_down_sync(0xffffffffu, acc, 1);
        if (!(t & 1)) g_h1h[(b * 8 + j) * 128 + (t >> 1)] = __floats2half2_rn(acc, hi);
    }
}

// ---------------- layer 1 FUSED softmax + aggregate: warp-per-head, barrier-free --
__global__ void k_fagg1(const float* __restrict__ b1) {
    __shared__ float sw[4][CH1];
    __shared__ int   si[4][CH1];
    int d = blockIdx.x;
    int t = threadIdx.x;              // 128; warp h owns head h and channels [32h,32h+32)
    int lane = t & 31, h = t >> 5;
    int beg = g_off[d], end = g_off[d + 1];
    float ad = g_ad1[d * 4 + h];
    float* swh = sw[h];
    int* sih = si[h];
    float gm = NEG_INF, gs = 0.f, ax = 0.f, ay = 0.f;
    for (int cb = beg; cb < end; cb += CH1) {
        int cnt = min(end - cb, CH1);
        float m = NEG_INF;
        for (int e = lane; e < cnt; e += 32) {
            int s = g_eid[cb + e];
            sih[e] = s;
            float lg = lrelu(g_as1[s * 4 + h] + ad);
            swh[e] = lg;
            m = fmaxf(m, lg);
        }
#pragma unroll
        for (int o = 16; o > 0; o >>= 1) m = fmaxf(m, __shfl_xor_sync(0xffffffffu, m, o));
        float ss = 0.f;
        for (int e = lane; e < cnt; e += 32) {
            float w = __expf(swh[e] - m);
            swh[e] = w;
            ss += w;
        }
#pragma unroll
        for (int o = 16; o > 0; o >>= 1) ss += __shfl_xor_sync(0xffffffffu, ss, o);
        __syncwarp();
        // gather: this warp's 32 half2 channels (c2 = t)
        float cax = 0.f, cay = 0.f;
        int e = 0;
        for (; e + 4 <= cnt; e += 4) {
            int i0 = sih[e], i1 = sih[e + 1], i2 = sih[e + 2], i3 = sih[e + 3];
            float w0 = swh[e], w1 = swh[e + 1], w2 = swh[e + 2], w3 = swh[e + 3];
            float2 v0 = __half22float2(g_h1h[i0 * 128 + t]);
            float2 v1 = __half22float2(g_h1h[i1 * 128 + t]);
            float2 v2 = __half22float2(g_h1h[i2 * 128 + t]);
            float2 v3 = __half22float2(g_h1h[i3 * 128 + t]);
            cax += w0 * v0.x + w1 * v1.x + w2 * v2.x + w3 * v3.x;
            cay += w0 * v0.y + w1 * v1.y + w2 * v2.y + w3 * v3.y;
        }
        for (; e < cnt; e++) {
            float w = swh[e];
            float2 v = __half22float2(g_h1h[sih[e] * 128 + t]);
            cax += w * v.x; cay += w * v.y;
        }
        float nm = fmaxf(gm, m);
        float f = __expf(gm - nm), c = __expf(m - nm);
        gs = gs * f + ss * c;
        ax = ax * f + cax * c;
        ay = ay * f + cay * c;
        gm = nm;
        __syncwarp();
    }
    float inv = 1.f / (gs + 1e-16f);
    float2 bb = reinterpret_cast<const float2*>(b1)[t];
    float ox = elu(ax * inv + bb.x);
    float oy = elu(ay * inv + bb.y);
    g_o1h[d * 128 + t] = __floats2half2_rn(ox, oy);
}

// ---------------- layer 2 GEMM (tensor cores) + fused alpha2 epilogue -------------
#define MMA16816(C, A0, A1, A2, A3, B0, B1)                                   \
    asm volatile("mma.sync.aligned.m16n8k16.row.col.f32.f16.f16.f32 "          \
        "{%0,%1,%2,%3}, {%4,%5,%6,%7}, {%8,%9}, {%0,%1,%2,%3};"                \
        : "+f"(C[0]), "+f"(C[1]), "+f"(C[2]), "+f"(C[3])                       \
        : "r"(A0), "r"(A1), "r"(A2), "r"(A3), "r"(B0), "r"(B1))

__global__ void k_gemm2() {
    __shared__ __align__(16) __half sA[64 * 256];
    __shared__ __align__(16) __half sW[64 * 256];
    __shared__ float svs[256], svd[256];
    int t = threadIdx.x;               // 128
    int base = blockIdx.x * 64;
    const uint4* gA = reinterpret_cast<const uint4*>(g_o1h) + base * 32;
    const uint4* gW = reinterpret_cast<const uint4*>(g_W2h);
    svs[t] = g_v2s[t]; svs[t + 128] = g_v2s[t + 128];
    svd[t] = g_v2d[t]; svd[t + 128] = g_v2d[t + 128];
#pragma unroll
    for (int j = 0; j < 16; j++) {
        int i = j * 128 + t;
        int r = i >> 5, c = i & 31;
        int sc = c ^ (r & 7);
        *reinterpret_cast<uint4*>(&sA[r * 256 + sc * 8]) = gA[i];
        *reinterpret_cast<uint4*>(&sW[r * 256 + sc * 8]) = gW[i];
    }
    __syncthreads();
    int lane = t & 31, warp = t >> 5;
    int m0 = warp * 16;
    float acc[8][4];
#pragma unroll
    for (int i = 0; i < 8; i++)
#pragma unroll
        for (int j = 0; j < 4; j++) acc[i][j] = 0.f;

    int arow = m0 + (lane & 7) + ((lane >> 3) & 1) * 8;
    int akc  = (lane >> 4);
    int brin = ((lane >> 4) & 1) * 8 + (lane & 7);
    int bkc  = (lane >> 3) & 1;
#pragma unroll
    for (int kt = 0; kt < 16; kt++) {
        int ac = kt * 2 + akc;
        uint32_t aaddr = su32(&sA[arow * 256 + ((ac ^ (arow & 7)) << 3)]);
        uint32_t a0, a1, a2, a3;
        asm volatile("ldmatrix.sync.aligned.m8n8.x4.shared.b16 {%0,%1,%2,%3}, [%4];"
            : "=r"(a0), "=r"(a1), "=r"(a2), "=r"(a3) : "r"(aaddr));
#pragma unroll
        for (int og = 0; og < 4; og++) {
            int brow = og * 16 + brin;
            int bc = kt * 2 + bkc;
            uint32_t baddr = su32(&sW[brow * 256 + ((bc ^ (brow & 7)) << 3)]);
            uint32_t b0, b1, b2, b3;
            // W2 is [o][k] row-major = K x N col-major: plain (no .trans) B fragment
            asm volatile("ldmatrix.sync.aligned.m8n8.x4.shared.b16 {%0,%1,%2,%3}, [%4];"
                : "=r"(b0), "=r"(b1), "=r"(b2), "=r"(b3) : "r"(baddr));
            MMA16816(acc[og * 2],     a0, a1, a2, a3, b0, b1);
            MMA16816(acc[og * 2 + 1], a0, a1, a2, a3, b2, b3);
        }
    }
    int r0 = base + m0 + (lane >> 2);
    int cq = lane & 3;
#pragma unroll
    for (int ot = 0; ot < 8; ot++) {
        g_h2h[r0 * 32 + ot * 4 + cq]       = __floats2half2_rn(acc[ot][0], acc[ot][1]);
        g_h2h[(r0 + 8) * 32 + ot * 4 + cq] = __floats2half2_rn(acc[ot][2], acc[ot][3]);
    }
    // ---- alpha2 epilogue: 2 threads per node over the sA tile ----
    {
        int n = t >> 1, half = t & 1;
        const __half2* sa2 = reinterpret_cast<const __half2*>(sA);
        float a = 0.f, b = 0.f;
        int kk0 = half * 64;             // half2 index range [kk0, kk0+64)
#pragma unroll 8
        for (int kk = kk0; kk < kk0 + 64; kk++) {
            int c = kk >> 2, w2 = kk & 3;
            float2 v = __half22float2(sa2[n * 128 + ((c ^ (n & 7)) << 2) + w2]);
            a += v.x * svs[2 * kk] + v.y * svs[2 * kk + 1];
            b += v.x * svd[2 * kk] + v.y * svd[2 * kk + 1];
        }
        a += __shfl_xor_sync(0xffffffffu, a, 1);
        b += __shfl_xor_sync(0xffffffffu, b, 1);
        if (half == 0 && base + n < NN) { g_as2[base + n] = a; g_ad2[base + n] = b; }
    }
}

// ---------------- layer 2 FUSED softmax + aggregate (warp per dst) ------------------
__global__ void k_fagg2(const float* __restrict__ b2) {
    __shared__ float sw[8][CH2];
    __shared__ int   si[8][CH2];
    int wid = threadIdx.x >> 5, lane = threadIdx.x & 31;
    int d = blockIdx.x * 8 + wid;
    int beg = g_off[d], end = g_off[d + 1];
    float ad = g_ad2[d];
    float gmv = NEG_INF, gsv = 0.f, ax = 0.f, ay = 0.f;
    for (int cb = beg; cb < end; cb += CH2) {
        int cnt = min(end - cb, CH2);
        float m = NEG_INF;
        for (int e = lane; e < cnt; e += 32) {
            int s = g_eid[cb + e];
            si[wid][e] = s;
            float lg = lrelu(g_as2[s] + ad);
            sw[wid][e] = lg;
            m = fmaxf(m, lg);
        }
#pragma unroll
        for (int o = 16; o > 0; o >>= 1) m = fmaxf(m, __shfl_xor_sync(0xffffffffu, m, o));
        float ssum = 0.f;
        for (int e = lane; e < cnt; e += 32) {
            float w = __expf(sw[wid][e] - m);
            sw[wid][e] = w;
            ssum += w;
        }
#pragma unroll
        for (int o = 16; o > 0; o >>= 1) ssum += __shfl_xor_sync(0xffffffffu, ssum, o);
        __syncwarp();
        float cax = 0.f, cay = 0.f;
        const float* swh = sw[wid];
        const int* sih = si[wid];
        int e = 0;
        for (; e + 4 <= cnt; e += 4) {
            int i0 = sih[e], i1 = sih[e + 1], i2 = sih[e + 2], i3 = sih[e + 3];
            float w0 = swh[e], w1 = swh[e + 1], w2 = swh[e + 2], w3 = swh[e + 3];
            float2 v0 = __half22float2(g_h2h[i0 * 32 + lane]);
            float2 v1 = __half22float2(g_h2h[i1 * 32 + lane]);
            float2 v2 = __half22float2(g_h2h[i2 * 32 + lane]);
            float2 v3 = __half22float2(g_h2h[i3 * 32 + lane]);
            cax += w0 * v0.x + w1 * v1.x + w2 * v2.x + w3 * v3.x;
            cay += w0 * v0.y + w1 * v1.y + w2 * v2.y + w3 * v3.y;
        }
        for (; e < cnt; e++) {
            float w = swh[e];
            float2 v = __half22float2(g_h2h[sih[e] * 32 + lane]);
            cax += w * v.x; cay += w * v.y;
        }
        float nm = fmaxf(gmv, m);
        float f = __expf(gmv - nm), c = __expf(m - nm);
        gsv = gsv * f + ssum * c;
        ax = ax * f + cax * c;
        ay = ay * f + cay * c;
        gmv = nm;
        __syncwarp();
    }
    float inv = 1.f / (gsv + 1e-16f);
    float2 bb = reinterpret_cast<const float2*>(b2)[lane];
    float2 o;
    o.x = elu(ax * inv + bb.x);
    o.y = elu(ay * inv + bb.y);
    reinterpret_cast<float2*>(g_o2)[d * 32 + lane] = o;
}

// ---------------- final projection (64 -> 1) ----------------------------------------
__global__ void k_final(const float* __restrict__ fw, const float* __restrict__ fb,
                        float* __restrict__ out) {
    int g = blockIdx.x * blockDim.x + threadIdx.x;
    int n = g >> 5, lane = g & 31;
    if (n >= NN) return;
    float v = g_o2[n * 64 + lane] * fw[lane] + g_o2[n * 64 + 32 + lane] * fw[32 + lane];
#pragma unroll
    for (int s = 16; s > 0; s >>= 1) v += __shfl_down_sync(0xffffffffu, v, s);
    if (lane == 0) out[n] = v + fb[0];
}

// ---------------- launch --------------------------------------------------------------
extern "C" void kernel_launch(void* const* d_in, const int* in_sizes, int n_in,
                              void* d_out, int out_size) {
    const float* x   = (const float*)d_in[0];
    const int*   ei  = (const int*)d_in[1];
    const float* W1  = (const float*)d_in[2];
    const float* as1 = (const float*)d_in[3];
    const float* ad1 = (const float*)d_in[4];
    const float* b1  = (const float*)d_in[5];
    const float* W2  = (const float*)d_in[6];
    const float* as2 = (const float*)d_in[7];
    const float* ad2 = (const float*)d_in[8];
    const float* b2  = (const float*)d_in[9];
    const float* fw  = (const float*)d_in[10];
    const float* fb  = (const float*)d_in[11];
    float*       out = (float*)d_out;

    k_init<<<NPART, 256>>>(ei);
    k_convert<<<(ET + 255) / 256, 256>>>(ei);
    k_scan_part<<<NPART, 256>>>();
    k_scan_mid<<<1, 256>>>();
    k_scan_fin<<<NPART, 256>>>();
    k_scatter<<<(ET + 255) / 256, 256>>>(ei);
    k_prew<<<1, 256>>>(W1, as1, ad1, W2, as2, ad2);
    k_gemm1<<<NN / 8, 256>>>(x, W1);
    k_fagg1<<<NN, 128>>>(b1);
    k_gemm2<<<NN2 / 64, 128>>>();
    k_fagg2<<<NN / 8, 256>>>(b2);
    k_final<<<(NN * 32 + 255) / 256, 256>>>(fw, fb, out);
}

// round 10
// speedup vs baseline: 7.0139x; 1.1197x over previous
#include <cuda_runtime.h>
#include <cuda_fp16.h>
#include <stdint.h>
#include <math.h>

#define NN 50000
#define NN2 50048          // padded to multiple of 64 for gemm2 tiles
#define FE 800000
#define ET (FE + NN)
#define NPART 196          // ceil(NN/256)
#define CH1 256
#define CH2 256

// ---------------- scratch ----------------------------------------------------
__device__ __half2 g_h1h[NN * 128];    // layer1 features fp16 (gather-only)
__device__ __half2 g_o1h[NN2 * 128];   // elu(layer1 out) fp16 (gemm2 A)
__device__ float   g_as1[NN * 4];
__device__ float   g_ad1[NN * 4];
__device__ __half  g_W2h[64 * 256];    // W2 fp16
__device__ __half2 g_h2h[NN2 * 32];    // layer2 pre-agg features fp16
__device__ float   g_as2[NN];
__device__ float   g_ad2[NN];
__device__ int     g_eid[ET];
__device__ int     g_cnt[NN];
__device__ int     g_off[NN + 1];
__device__ int     g_cur[NN];
__device__ int     g_part[NPART];
__device__ int     g_is64;
__device__ float   g_ws1s[64];
__device__ float   g_ws1d[64];
__device__ float   g_v2s[256];
__device__ float   g_v2d[256];

__device__ __forceinline__ float lrelu(float v) { return v > 0.f ? v : 0.2f * v; }
__device__ __forceinline__ float elu(float v)   { return v > 0.f ? v : expm1f(v); }
__device__ __forceinline__ uint32_t su32(const void* p) {
    return (uint32_t)__cvta_generic_to_shared(p);
}
#define NEG_INF __int_as_float(0xff800000)

// ---------------- setup: zero counters + dtype detect + weight folds ------------
__global__ void k_setup(const int* __restrict__ ei32,
                        const float* __restrict__ W1,
                        const float* __restrict__ as1, const float* __restrict__ ad1,
                        const float* __restrict__ W2,
                        const float* __restrict__ as2, const float* __restrict__ ad2) {
    int t = threadIdx.x;
    int i = blockIdx.x * blockDim.x + t;
    if (i < NN) g_cnt[i] = 0;
    if (blockIdx.x == 0) {
        int nz = 0;
        for (int k = t; k < 1024; k += 256) nz |= ei32[2 * k + 1];
        int any = __syncthreads_or(nz);
        if (t == 0) g_is64 = (any == 0);
    } else if (blockIdx.x == 1) {
        if (t < 64) {
            int h = t >> 4, ii = t & 15;
            float s = 0.f, d = 0.f;
            for (int c = 0; c < 64; c++) {
                float w = W1[(h * 64 + c) * 16 + ii];
                s += as1[h * 64 + c] * w;
                d += ad1[h * 64 + c] * w;
            }
            g_ws1s[t] = s; g_ws1d[t] = d;
        }
        {
            float s = 0.f, d = 0.f;
            for (int o = 0; o < 64; o++) {
                float w = W2[o * 256 + t];
                s += as2[o] * w;
                d += ad2[o] * w;
            }
            g_v2s[t] = s; g_v2d[t] = d;
        }
        for (int j = 0; j < 64; j++) {
            int idx = j * 256 + t;
            g_W2h[idx] = __float2half(W2[idx]);
        }
    }
}

// ---------------- layer 1 GEMM + fused logits + fused edge counting --------------
__global__ void k_gemm1(const float* __restrict__ x, const float* __restrict__ W1,
                        const int* __restrict__ ei32) {
    __shared__ float xs[128];
    int t = threadIdx.x, b = blockIdx.x;
    // fused in-degree counting: global thread id covers all edges
    {
        int i = b * 256 + t;
        if (i < ET) {
            int d;
            if (i < FE) d = g_is64 ? ei32[2 * (FE + i)] : ei32[FE + i];
            else        d = i - FE;
            atomicAdd(&g_cnt[d], 1);
        }
    }
    if (t < 128) xs[t] = x[b * 128 + t];
    __syncthreads();
    if (t < 64) {   // logits: 8 nodes x 4 heads x {src,dst}
        int j = t >> 3, h = (t >> 1) & 3, sd = t & 1;
        const float* wv = (sd ? g_ws1d : g_ws1s) + h * 16;
        const float* xv = xs + j * 16;
        float a = 0.f;
#pragma unroll
        for (int i = 0; i < 16; i++) a += xv[i] * wv[i];
        int n = b * 8 + j;
        if (sd) g_ad1[n * 4 + h] = a; else g_as1[n * 4 + h] = a;
    }
    const float4* W4 = reinterpret_cast<const float4*>(W1) + t * 4;
    float4 w0 = W4[0], w1 = W4[1], w2 = W4[2], w3 = W4[3];
#pragma unroll
    for (int j = 0; j < 8; j++) {
        const float* xv = xs + j * 16;
        float acc = xv[0] * w0.x + xv[1] * w0.y + xv[2] * w0.z + xv[3] * w0.w
                  + xv[4] * w1.x + xv[5] * w1.y + xv[6] * w1.z + xv[7] * w1.w
                  + xv[8] * w2.x + xv[9] * w2.y + xv[10] * w2.z + xv[11] * w2.w
                  + xv[12] * w3.x + xv[13] * w3.y + xv[14] * w3.z + xv[15] * w3.w;
        float hi = __shfl_down_sync(0xffffffffu, acc, 1);
        if (!(t & 1)) g_h1h[(b * 8 + j) * 128 + (t >> 1)] = __floats2half2_rn(acc, hi);
    }
}

// ---------------- scan part: per-256-block sums -----------------------------------
__global__ void k_scan_part() {
    __shared__ int sm[256];
    int b = blockIdx.x, t = threadIdx.x, i = b * 256 + t;
    sm[t] = (i < NN) ? g_cnt[i] : 0;
    __syncthreads();
#pragma unroll
    for (int s = 128; s > 0; s >>= 1) { if (t < s) sm[t] += sm[t + s]; __syncthreads(); }
    if (t == 0) g_part[b] = sm[0];
}
// ---------------- scan finish: redundant partial-scan + local scan ----------------
__global__ void k_scan_fin2() {
    __shared__ int sp[256];
    __shared__ int sm[256];
    int b = blockIdx.x, t = threadIdx.x, i = b * 256 + t;
    sp[t] = (t < NPART) ? g_part[t] : 0;
    int v = (i < NN) ? g_cnt[i] : 0;
    sm[t] = v;
    __syncthreads();
#pragma unroll
    for (int s = 1; s < 256; s <<= 1) {
        int a = (t >= s) ? sp[t - s] : 0;
        int c = (t >= s) ? sm[t - s] : 0;
        __syncthreads();
        sp[t] += a; sm[t] += c;
        __syncthreads();
    }
    int base = (b > 0) ? sp[b - 1] : 0;      // exclusive prefix of parts
    if (i < NN) {
        int off = base + sm[t] - v;
        g_off[i] = off; g_cur[i] = off;
    }
    if (b == 0 && t == 0) g_off[NN] = ET;
}
__global__ void k_scatter(const int* __restrict__ ei32) {
    int i = blockIdx.x * blockDim.x + threadIdx.x;
    if (i >= ET) return;
    int s, d;
    if (i < FE) {
        if (g_is64) { s = ei32[2 * i]; d = ei32[2 * (FE + i)]; }
        else        { s = ei32[i];     d = ei32[FE + i]; }
    } else { s = i - FE; d = s; }
    int pos = atomicAdd(&g_cur[d], 1);
    g_eid[pos] = s;
}

// ---------------- layer 1 FUSED softmax + aggregate: warp-per-head, barrier-free --
__global__ void k_fagg1(const float* __restrict__ b1) {
    __shared__ float sw[4][CH1];
    __shared__ int   si[4][CH1];
    int d = blockIdx.x;
    int t = threadIdx.x;              // 128; warp h owns head h and channels [32h,32h+32)
    int lane = t & 31, h = t >> 5;
    int beg = g_off[d], end = g_off[d + 1];
    float ad = g_ad1[d * 4 + h];
    float* swh = sw[h];
    int* sih = si[h];
    float gm = NEG_INF, gs = 0.f, ax = 0.f, ay = 0.f;
    for (int cb = beg; cb < end; cb += CH1) {
        int cnt = min(end - cb, CH1);
        float m = NEG_INF;
        for (int e = lane; e < cnt; e += 32) {
            int s = g_eid[cb + e];
            sih[e] = s;
            float lg = lrelu(g_as1[s * 4 + h] + ad);
            swh[e] = lg;
            m = fmaxf(m, lg);
        }
#pragma unroll
        for (int o = 16; o > 0; o >>= 1) m = fmaxf(m, __shfl_xor_sync(0xffffffffu, m, o));
        float ss = 0.f;
        for (int e = lane; e < cnt; e += 32) {
            float w = __expf(swh[e] - m);
            swh[e] = w;
            ss += w;
        }
#pragma unroll
        for (int o = 16; o > 0; o >>= 1) ss += __shfl_xor_sync(0xffffffffu, ss, o);
        __syncwarp();
        float cax = 0.f, cay = 0.f;
        int e = 0;
        for (; e + 4 <= cnt; e += 4) {
            int i0 = sih[e], i1 = sih[e + 1], i2 = sih[e + 2], i3 = sih[e + 3];
            float w0 = swh[e], w1 = swh[e + 1], w2 = swh[e + 2], w3 = swh[e + 3];
            float2 v0 = __half22float2(g_h1h[i0 * 128 + t]);
            float2 v1 = __half22float2(g_h1h[i1 * 128 + t]);
            float2 v2 = __half22float2(g_h1h[i2 * 128 + t]);
            float2 v3 = __half22float2(g_h1h[i3 * 128 + t]);
            cax += w0 * v0.x + w1 * v1.x + w2 * v2.x + w3 * v3.x;
            cay += w0 * v0.y + w1 * v1.y + w2 * v2.y + w3 * v3.y;
        }
        for (; e < cnt; e++) {
            float w = swh[e];
            float2 v = __half22float2(g_h1h[sih[e] * 128 + t]);
            cax += w * v.x; cay += w * v.y;
        }
        float nm = fmaxf(gm, m);
        float f = __expf(gm - nm), c = __expf(m - nm);
        gs = gs * f + ss * c;
        ax = ax * f + cax * c;
        ay = ay * f + cay * c;
        gm = nm;
        __syncwarp();
    }
    float inv = 1.f / (gs + 1e-16f);
    float2 bb = reinterpret_cast<const float2*>(b1)[t];
    float ox = elu(ax * inv + bb.x);
    float oy = elu(ay * inv + bb.y);
    g_o1h[d * 128 + t] = __floats2half2_rn(ox, oy);
}

// ---------------- layer 2 GEMM (tensor cores) + fused alpha2 epilogue -------------
#define MMA16816(C, A0, A1, A2, A3, B0, B1)                                   \
    asm volatile("mma.sync.aligned.m16n8k16.row.col.f32.f16.f16.f32 "          \
        "{%0,%1,%2,%3}, {%4,%5,%6,%7}, {%8,%9}, {%0,%1,%2,%3};"                \
        : "+f"(C[0]), "+f"(C[1]), "+f"(C[2]), "+f"(C[3])                       \
        : "r"(A0), "r"(A1), "r"(A2), "r"(A3), "r"(B0), "r"(B1))

__global__ void k_gemm2() {
    __shared__ __align__(16) __half sA[64 * 256];
    __shared__ __align__(16) __half sW[64 * 256];
    __shared__ float svs[256], svd[256];
    int t = threadIdx.x;               // 128
    int base = blockIdx.x * 64;
    const uint4* gA = reinterpret_cast<const uint4*>(g_o1h) + base * 32;
    const uint4* gW = reinterpret_cast<const uint4*>(g_W2h);
    svs[t] = g_v2s[t]; svs[t + 128] = g_v2s[t + 128];
    svd[t] = g_v2d[t]; svd[t + 128] = g_v2d[t + 128];
#pragma unroll
    for (int j = 0; j < 16; j++) {
        int i = j * 128 + t;
        int r = i >> 5, c = i & 31;
        int sc = c ^ (r & 7);
        *reinterpret_cast<uint4*>(&sA[r * 256 + sc * 8]) = gA[i];
        *reinterpret_cast<uint4*>(&sW[r * 256 + sc * 8]) = gW[i];
    }
    __syncthreads();
    int lane = t & 31, warp = t >> 5;
    int m0 = warp * 16;
    float acc[8][4];
#pragma unroll
    for (int i = 0; i < 8; i++)
#pragma unroll
        for (int j = 0; j < 4; j++) acc[i][j] = 0.f;

    int arow = m0 + (lane & 7) + ((lane >> 3) & 1) * 8;
    int akc  = (lane >> 4);
    int brin = ((lane >> 4) & 1) * 8 + (lane & 7);
    int bkc  = (lane >> 3) & 1;
#pragma unroll
    for (int kt = 0; kt < 16; kt++) {
        int ac = kt * 2 + akc;
        uint32_t aaddr = su32(&sA[arow * 256 + ((ac ^ (arow & 7)) << 3)]);
        uint32_t a0, a1, a2, a3;
        asm volatile("ldmatrix.sync.aligned.m8n8.x4.shared.b16 {%0,%1,%2,%3}, [%4];"
            : "=r"(a0), "=r"(a1), "=r"(a2), "=r"(a3) : "r"(aaddr));
#pragma unroll
        for (int og = 0; og < 4; og++) {
            int brow = og * 16 + brin;
            int bc = kt * 2 + bkc;
            uint32_t baddr = su32(&sW[brow * 256 + ((bc ^ (brow & 7)) << 3)]);
            uint32_t b0, b1, b2, b3;
            // W2 is [o][k] row-major = K x N col-major: plain (no .trans) B fragment
            asm volatile("ldmatrix.sync.aligned.m8n8.x4.shared.b16 {%0,%1,%2,%3}, [%4];"
                : "=r"(b0), "=r"(b1), "=r"(b2), "=r"(b3) : "r"(baddr));
            MMA16816(acc[og * 2],     a0, a1, a2, a3, b0, b1);
            MMA16816(acc[og * 2 + 1], a0, a1, a2, a3, b2, b3);
        }
    }
    int r0 = base + m0 + (lane >> 2);
    int cq = lane & 3;
#pragma unroll
    for (int ot = 0; ot < 8; ot++) {
        g_h2h[r0 * 32 + ot * 4 + cq]       = __floats2half2_rn(acc[ot][0], acc[ot][1]);
        g_h2h[(r0 + 8) * 32 + ot * 4 + cq] = __floats2half2_rn(acc[ot][2], acc[ot][3]);
    }
    // ---- alpha2 epilogue: 2 threads per node over the sA tile ----
    {
        int n = t >> 1, half = t & 1;
        const __half2* sa2 = reinterpret_cast<const __half2*>(sA);
        float a = 0.f, b = 0.f;
        int kk0 = half * 64;
#pragma unroll 8
        for (int kk = kk0; kk < kk0 + 64; kk++) {
            int c = kk >> 2, w2 = kk & 3;
            float2 v = __half22float2(sa2[n * 128 + ((c ^ (n & 7)) << 2) + w2]);
            a += v.x * svs[2 * kk] + v.y * svs[2 * kk + 1];
            b += v.x * svd[2 * kk] + v.y * svd[2 * kk + 1];
        }
        a += __shfl_xor_sync(0xffffffffu, a, 1);
        b += __shfl_xor_sync(0xffffffffu, b, 1);
        if (half == 0 && base + n < NN) { g_as2[base + n] = a; g_ad2[base + n] = b; }
    }
}

// ---------------- layer 2 FUSED softmax + aggregate + FINAL projection -------------
__global__ void k_fagg2(const float* __restrict__ b2,
                        const float* __restrict__ fw, const float* __restrict__ fb,
                        float* __restrict__ out) {
    __shared__ float sw[8][CH2];
    __shared__ int   si[8][CH2];
    int wid = threadIdx.x >> 5, lane = threadIdx.x & 31;
    int d = blockIdx.x * 8 + wid;
    int beg = g_off[d], end = g_off[d + 1];
    float ad = g_ad2[d];
    float gmv = NEG_INF, gsv = 0.f, ax = 0.f, ay = 0.f;
    for (int cb = beg; cb < end; cb += CH2) {
        int cnt = min(end - cb, CH2);
        float m = NEG_INF;
        for (int e = lane; e < cnt; e += 32) {
            int s = g_eid[cb + e];
            si[wid][e] = s;
            float lg = lrelu(g_as2[s] + ad);
            sw[wid][e] = lg;
            m = fmaxf(m, lg);
        }
#pragma unroll
        for (int o = 16; o > 0; o >>= 1) m = fmaxf(m, __shfl_xor_sync(0xffffffffu, m, o));
        float ssum = 0.f;
        for (int e = lane; e < cnt; e += 32) {
            float w = __expf(sw[wid][e] - m);
            sw[wid][e] = w;
            ssum += w;
        }
#pragma unroll
        for (int o = 16; o > 0; o >>= 1) ssum += __shfl_xor_sync(0xffffffffu, ssum, o);
        __syncwarp();
        float cax = 0.f, cay = 0.f;
        const float* swh = sw[wid];
        const int* sih = si[wid];
        int e = 0;
        for (; e + 4 <= cnt; e += 4) {
            int i0 = sih[e], i1 = sih[e + 1], i2 = sih[e + 2], i3 = sih[e + 3];
            float w0 = swh[e], w1 = swh[e + 1], w2 = swh[e + 2], w3 = swh[e + 3];
            float2 v0 = __half22float2(g_h2h[i0 * 32 + lane]);
            float2 v1 = __half22float2(g_h2h[i1 * 32 + lane]);
            float2 v2 = __half22float2(g_h2h[i2 * 32 + lane]);
            float2 v3 = __half22float2(g_h2h[i3 * 32 + lane]);
            cax += w0 * v0.x + w1 * v1.x + w2 * v2.x + w3 * v3.x;
            cay += w0 * v0.y + w1 * v1.y + w2 * v2.y + w3 * v3.y;
        }
        for (; e < cnt; e++) {
            float w = swh[e];
            float2 v = __half22float2(g_h2h[sih[e] * 32 + lane]);
            cax += w * v.x; cay += w * v.y;
        }
        float nm = fmaxf(gmv, m);
        float f = __expf(gmv - nm), c = __expf(m - nm);
        gsv = gsv * f + ssum * c;
        ax = ax * f + cax * c;
        ay = ay * f + cay * c;
        gmv = nm;
        __syncwarp();
    }
    float inv = 1.f / (gsv + 1e-16f);
    float2 bb = reinterpret_cast<const float2*>(b2)[lane];
    float ox = elu(ax * inv + bb.x);
    float oy = elu(ay * inv + bb.y);
    // fused final projection: out[d] = sum_c o2[c]*fw[c] + fb
    float2 fwv = reinterpret_cast<const float2*>(fw)[lane];
    float v = ox * fwv.x + oy * fwv.y;
#pragma unroll
    for (int o = 16; o > 0; o >>= 1) v += __shfl_xor_sync(0xffffffffu, v, o);
    if (lane == 0) out[d] = v + fb[0];
}

// ---------------- launch --------------------------------------------------------------
extern "C" void kernel_launch(void* const* d_in, const int* in_sizes, int n_in,
                              void* d_out, int out_size) {
    const float* x   = (const float*)d_in[0];
    const int*   ei  = (const int*)d_in[1];
    const float* W1  = (const float*)d_in[2];
    const float* as1 = (const float*)d_in[3];
    const float* ad1 = (const float*)d_in[4];
    const float* b1  = (const float*)d_in[5];
    const float* W2  = (const float*)d_in[6];
    const float* as2 = (const float*)d_in[7];
    const float* ad2 = (const float*)d_in[8];
    const float* b2  = (const float*)d_in[9];
    const float* fw  = (const float*)d_in[10];
    const float* fb  = (const float*)d_in[11];
    float*       out = (float*)d_out;

    k_setup<<<NPART, 256>>>(ei, W1, as1, ad1, W2, as2, ad2);
    k_gemm1<<<NN / 8, 256>>>(x, W1, ei);
    k_scan_part<<<NPART, 256>>>();
    k_scan_fin2<<<NPART, 256>>>();
    k_scatter<<<(ET + 255) / 256, 256>>>(ei);
    k_fagg1<<<NN, 128>>>(b1);
    k_gemm2<<<NN2 / 64, 128>>>();
    k_fagg2<<<NN / 8, 256>>>(b2, fw, fb, out);
}